// round 1
// baseline (speedup 1.0000x reference)
#include <cuda_runtime.h>
#include <math.h>

// Problem constants
#define Bc 16
#define Nc 5
#define Tc 10
#define Hc 512
#define Ec 250
#define Vc 30000
#define Fc 2048
#define H4 2048
#define H2 1024
#define NTB (Nc*Tc*Bc)   // 800

// ---------------- device scratch (no cudaMalloc allowed) ----------------
__device__ float g_tmp[Bc*H2];            // MLP intermediate
__device__ float g_h0[Bc*Hc];             // image h
__device__ float g_c0[Bc*Hc];             // image c
__device__ float g_sh[4*2*Bc*Hc];         // state h, 4 slots x 2 parity
__device__ float g_sc[4*Bc*Hc];           // state c, 4 slots (in-place safe)
__device__ float g_x0[NTB*Ec];            // gathered embeddings (n,t,b,e)
__device__ float g_xg0[2*NTB*H4];         // precomputed layer0 gates (+bias), per dir
__device__ float g_x1[Tc*Bc*H2];          // layer0 outputs concat [of|ob], time-indexed
__device__ float g_out1[NTB*H2];          // layer1 outputs (n,tau,b,[o1f|o1b])
__device__ float g_WhhT[4*H4*Hc];         // transposed Whh: 0=0f 1=0b 2=1f 3=1b  [2048][512]
__device__ float g_WihT[2*H4*H2];         // transposed Wih1: 0=f 1=b              [2048][1024]

// ---------------- generic fp32 GEMM: C = A[MxK] @ W[KxN] + bias (opt relu) ----------------
__global__ __launch_bounds__(256) void sgemm_kernel(
    const float* __restrict__ A, const float* __restrict__ W,
    const float* __restrict__ bias, float* __restrict__ C,
    int M, int N, int K, int relu)
{
    __shared__ float As[16][64];
    __shared__ float Bs[16][64];
    int bm = blockIdx.y * 64, bn = blockIdx.x * 64;
    int tid = threadIdx.x;
    int tm = (tid >> 4) << 2;
    int tn = (tid & 15) << 2;
    float acc[4][4] = {};
    for (int k0 = 0; k0 < K; k0 += 16) {
        #pragma unroll
        for (int e = 0; e < 4; e++) {
            int idx = tid + e * 256;
            int r = idx >> 4, c = idx & 15;
            int gr = bm + r, gc = k0 + c;
            float v = 0.f;
            if (gr < M && gc < K) v = A[(size_t)gr * K + gc];
            As[c][r] = v;
        }
        #pragma unroll
        for (int e = 0; e < 4; e++) {
            int idx = tid + e * 256;
            int r = idx >> 6, c = idx & 63;
            int gr = k0 + r, gc = bn + c;
            float v = 0.f;
            if (gr < K && gc < N) v = W[(size_t)gr * N + gc];
            Bs[r][c] = v;
        }
        __syncthreads();
        #pragma unroll
        for (int kk = 0; kk < 16; kk++) {
            float4 a4 = *(const float4*)&As[kk][tm];
            float4 b4 = *(const float4*)&Bs[kk][tn];
            float a[4] = {a4.x, a4.y, a4.z, a4.w};
            float b[4] = {b4.x, b4.y, b4.z, b4.w};
            #pragma unroll
            for (int i = 0; i < 4; i++)
                #pragma unroll
                for (int j = 0; j < 4; j++)
                    acc[i][j] = fmaf(a[i], b[j], acc[i][j]);
        }
        __syncthreads();
    }
    #pragma unroll
    for (int i = 0; i < 4; i++) {
        int gm = bm + tm + i;
        if (gm >= M) continue;
        #pragma unroll
        for (int j = 0; j < 4; j++) {
            int gn = bn + tn + j;
            if (gn >= N) continue;
            float v = acc[i][j] + bias[gn];
            if (relu) v = fmaxf(v, 0.f);
            C[(size_t)gm * N + gn] = v;
        }
    }
}

// ---------------- transpose: out[C][R] = in[R][C] ----------------
__global__ void transpose_k(const float* __restrict__ in, float* __restrict__ out, int R, int C)
{
    __shared__ float tile[32][33];
    int c0 = blockIdx.x * 32, r0 = blockIdx.y * 32;
    for (int j = threadIdx.y; j < 32; j += 8) {
        int r = r0 + j, c = c0 + threadIdx.x;
        tile[j][threadIdx.x] = (r < R && c < C) ? in[(size_t)r * C + c] : 0.f;
    }
    __syncthreads();
    for (int j = threadIdx.y; j < 32; j += 8) {
        int c = c0 + j, r = r0 + threadIdx.x;
        if (c < C && r < R) out[(size_t)c * R + r] = tile[threadIdx.x][j];
    }
}

// ---------------- embedding gather: g_x0[(n*T+t)*B+b][e] = emb[caps[b][n][t]][e] ----------------
__global__ void gather_k(const int* __restrict__ caps, const float* __restrict__ emb)
{
    int rid = blockIdx.x;          // 0..799
    int b = rid & 15;
    int nt = rid >> 4;             // n*10 + t
    int n = nt / Tc, t = nt % Tc;
    int tok = caps[b * (Nc * Tc) + n * Tc + t];
    const float* e = emb + (size_t)tok * Ec;
    float* o = g_x0 + (size_t)rid * Ec;
    for (int i = threadIdx.x; i < Ec; i += blockDim.x) o[i] = e[i];
}

// ---------------- broadcast image h/c into the 4 state slots (parity 0) ----------------
__global__ void bcast_state_k()
{
    int i = blockIdx.x * blockDim.x + threadIdx.x;
    if (i < Bc * Hc) {
        float h = g_h0[i], c = g_c0[i];
        #pragma unroll
        for (int s = 0; s < 4; s++) {
            g_sh[(s * 2 + 0) * (Bc * Hc) + i] = h;
            g_sc[s * (Bc * Hc) + i] = c;
        }
    }
}

// ---------------- one LSTM timestep, both directions (blockIdx.z = dir) ----------------
struct StepArgs {
    const float* Whh[2];    // transposed [2048][512]
    const float* pre[2];    // layer0: precomputed gates (B x 2048); layer1: unused
    const float* Wih[2];    // layer1: transposed [2048][1024]
    const float* bias[2];   // layer1 bias (2048)
    const float* xin[2];    // layer1 input rows (B x 1024)
    const float* h_in[2];
    float*       h_out[2];
    float*       c[2];      // in-place (owner-thread only)
    float*       out[2];    // h output location (per-batch stride out_stride, + dir col offset baked in)
    int out_stride;
    int layer1;
};

__global__ __launch_bounds__(512) void lstm_step(StepArgs a)
{
    int d   = blockIdx.z;
    int tid = threadIdx.x;          // 512 threads: 16 b x 8 k x 4 r-splits
    int b   = tid & 15;
    int kl  = (tid >> 4) & 7;
    int rs  = tid >> 7;             // 0..3
    int k   = blockIdx.x * 8 + kl;  // 0..511

    float acc0 = 0.f, acc1 = 0.f, acc2 = 0.f, acc3 = 0.f;

    // recurrent part: h (512) @ WhhT columns, r-chunk of 128
    {
        const float* Wt = a.Whh[d];
        const float4* h4 = (const float4*)(a.h_in[d] + b * Hc + rs * 128);
        const float4* w0 = (const float4*)(Wt + (size_t)(k)        * Hc + rs * 128);
        const float4* w1 = (const float4*)(Wt + (size_t)(k + 512)  * Hc + rs * 128);
        const float4* w2 = (const float4*)(Wt + (size_t)(k + 1024) * Hc + rs * 128);
        const float4* w3 = (const float4*)(Wt + (size_t)(k + 1536) * Hc + rs * 128);
        #pragma unroll 8
        for (int i = 0; i < 32; i++) {
            float4 h = h4[i];
            float4 w;
            w = w0[i]; acc0 += h.x*w.x + h.y*w.y + h.z*w.z + h.w*w.w;
            w = w1[i]; acc1 += h.x*w.x + h.y*w.y + h.z*w.z + h.w*w.w;
            w = w2[i]; acc2 += h.x*w.x + h.y*w.y + h.z*w.z + h.w*w.w;
            w = w3[i]; acc3 += h.x*w.x + h.y*w.y + h.z*w.z + h.w*w.w;
        }
    }
    // layer1: fold x1 (1024) @ WihT, r-chunk of 256
    if (a.layer1) {
        const float* Wt = a.Wih[d];
        const float4* x4 = (const float4*)(a.xin[d] + b * H2 + rs * 256);
        const float4* w0 = (const float4*)(Wt + (size_t)(k)        * H2 + rs * 256);
        const float4* w1 = (const float4*)(Wt + (size_t)(k + 512)  * H2 + rs * 256);
        const float4* w2 = (const float4*)(Wt + (size_t)(k + 1024) * H2 + rs * 256);
        const float4* w3 = (const float4*)(Wt + (size_t)(k + 1536) * H2 + rs * 256);
        #pragma unroll 8
        for (int i = 0; i < 64; i++) {
            float4 x = x4[i];
            float4 w;
            w = w0[i]; acc0 += x.x*w.x + x.y*w.y + x.z*w.z + x.w*w.w;
            w = w1[i]; acc1 += x.x*w.x + x.y*w.y + x.z*w.z + x.w*w.w;
            w = w2[i]; acc2 += x.x*w.x + x.y*w.y + x.z*w.z + x.w*w.w;
            w = w3[i]; acc3 += x.x*w.x + x.y*w.y + x.z*w.z + x.w*w.w;
        }
    }

    __shared__ float red[4][128][4];
    int pair = tid & 127;
    if (rs) {
        red[rs][pair][0] = acc0; red[rs][pair][1] = acc1;
        red[rs][pair][2] = acc2; red[rs][pair][3] = acc3;
    }
    __syncthreads();
    if (rs == 0) {
        acc0 += red[1][pair][0] + red[2][pair][0] + red[3][pair][0];
        acc1 += red[1][pair][1] + red[2][pair][1] + red[3][pair][1];
        acc2 += red[1][pair][2] + red[2][pair][2] + red[3][pair][2];
        acc3 += red[1][pair][3] + red[2][pair][3] + red[3][pair][3];
        float pi, pf, pg, po;
        if (a.layer1) {
            const float* bs = a.bias[d];
            pi = bs[k]; pf = bs[k + 512]; pg = bs[k + 1024]; po = bs[k + 1536];
        } else {
            const float* xg = a.pre[d] + (size_t)b * H4;
            pi = xg[k]; pf = xg[k + 512]; pg = xg[k + 1024]; po = xg[k + 1536];
        }
        float gi = acc0 + pi, gf = acc1 + pf, gg = acc2 + pg, go = acc3 + po;
        float si = 1.f / (1.f + expf(-gi));
        float sf = 1.f / (1.f + expf(-gf));
        float so = 1.f / (1.f + expf(-go));
        int idx = b * Hc + k;
        float cn = sf * a.c[d][idx] + si * tanhf(gg);
        float hn = so * tanhf(cn);
        a.c[d][idx]     = cn;
        a.h_out[d][idx] = hn;
        a.out[d][b * a.out_stride + k] = hn;
    }
}

// ---------------- host ----------------
extern "C" void kernel_launch(void* const* d_in, const int* in_sizes, int n_in,
                              void* d_out, int out_size)
{
    const float* img   = (const float*)d_in[0];
    const int*   caps  = (const int*)  d_in[1];
    const float* Wh1   = (const float*)d_in[2];
    const float* bh1   = (const float*)d_in[3];
    const float* Wh2   = (const float*)d_in[4];
    const float* bh2   = (const float*)d_in[5];
    const float* Wc1   = (const float*)d_in[6];
    const float* bc1   = (const float*)d_in[7];
    const float* Wc2   = (const float*)d_in[8];
    const float* bc2   = (const float*)d_in[9];
    const float* emb   = (const float*)d_in[10];
    const float* Wih0f = (const float*)d_in[11];
    const float* Whh0f = (const float*)d_in[12];
    const float* b0f   = (const float*)d_in[13];
    const float* Wih0b = (const float*)d_in[14];
    const float* Whh0b = (const float*)d_in[15];
    const float* b0b   = (const float*)d_in[16];
    const float* Wih1f = (const float*)d_in[17];
    const float* Whh1f = (const float*)d_in[18];
    const float* b1f   = (const float*)d_in[19];
    const float* Wih1b = (const float*)d_in[20];
    const float* Whh1b = (const float*)d_in[21];
    const float* b1b   = (const float*)d_in[22];
    const float* Wfc   = (const float*)d_in[23];
    const float* bfc   = (const float*)d_in[24];
    float* outp = (float*)d_out;

    // resolve scratch symbol addresses (pure queries; capture-safe)
    float *p_tmp, *p_h0, *p_c0, *p_x0, *p_xg0, *p_x1, *p_out1, *p_sh, *p_sc, *p_WhhT, *p_WihT;
    cudaGetSymbolAddress((void**)&p_tmp,  g_tmp);
    cudaGetSymbolAddress((void**)&p_h0,   g_h0);
    cudaGetSymbolAddress((void**)&p_c0,   g_c0);
    cudaGetSymbolAddress((void**)&p_x0,   g_x0);
    cudaGetSymbolAddress((void**)&p_xg0,  g_xg0);
    cudaGetSymbolAddress((void**)&p_x1,   g_x1);
    cudaGetSymbolAddress((void**)&p_out1, g_out1);
    cudaGetSymbolAddress((void**)&p_sh,   g_sh);
    cudaGetSymbolAddress((void**)&p_sc,   g_sc);
    cudaGetSymbolAddress((void**)&p_WhhT, g_WhhT);
    cudaGetSymbolAddress((void**)&p_WihT, g_WihT);

    const int SL = Bc * Hc;  // state slot size

    dim3 tb(32, 8);
    // transpose recurrent / layer1-input weights (needed every launch; cheap)
    transpose_k<<<dim3(H4/32, Hc/32), tb>>>(Whh0f, p_WhhT + 0 * (size_t)H4 * Hc, Hc, H4);
    transpose_k<<<dim3(H4/32, Hc/32), tb>>>(Whh0b, p_WhhT + 1 * (size_t)H4 * Hc, Hc, H4);
    transpose_k<<<dim3(H4/32, Hc/32), tb>>>(Whh1f, p_WhhT + 2 * (size_t)H4 * Hc, Hc, H4);
    transpose_k<<<dim3(H4/32, Hc/32), tb>>>(Whh1b, p_WhhT + 3 * (size_t)H4 * Hc, Hc, H4);
    transpose_k<<<dim3(H4/32, H2/32), tb>>>(Wih1f, p_WihT + 0 * (size_t)H4 * H2, H2, H4);
    transpose_k<<<dim3(H4/32, H2/32), tb>>>(Wih1b, p_WihT + 1 * (size_t)H4 * H2, H2, H4);

    // image MLPs: h then c (g_tmp reuse is stream-ordered)
    sgemm_kernel<<<dim3(H2/64, 1), 256>>>(img,   Wh1, bh1, p_tmp, Bc, H2, Fc, 1);
    sgemm_kernel<<<dim3(Hc/64, 1), 256>>>(p_tmp, Wh2, bh2, p_h0,  Bc, Hc, H2, 1);
    sgemm_kernel<<<dim3(H2/64, 1), 256>>>(img,   Wc1, bc1, p_tmp, Bc, H2, Fc, 1);
    sgemm_kernel<<<dim3(Hc/64, 1), 256>>>(p_tmp, Wc2, bc2, p_c0,  Bc, Hc, H2, 1);
    bcast_state_k<<<(Bc*Hc + 255)/256, 256>>>();

    // embeddings + layer0 input gates (reused by ALL 50 calls)
    gather_k<<<NTB, 256>>>(caps, emb);
    sgemm_kernel<<<dim3(H4/64, (NTB+63)/64), 256>>>(p_x0, Wih0f, b0f, p_xg0,                      NTB, H4, Ec, 0);
    sgemm_kernel<<<dim3(H4/64, (NTB+63)/64), 256>>>(p_x0, Wih0b, b0b, p_xg0 + (size_t)NTB * H4,   NTB, H4, Ec, 0);

    // sequential bilstm2 chain
    int par[4] = {0, 0, 0, 0};
    for (int t = 0; t < Tc; t++) {
        for (int n = 0; n < Nc; n++) {
            int L = t + 1;
            // ---- layer 0 (slots 0=fwd, 1=bwd) ----
            for (int s = 0; s < L; s++) {
                int tf = s, tbk = L - 1 - s;
                StepArgs a = {};
                a.layer1 = 0;
                a.out_stride = H2;
                a.Whh[0] = p_WhhT + 0 * (size_t)H4 * Hc;
                a.Whh[1] = p_WhhT + 1 * (size_t)H4 * Hc;
                a.pre[0] = p_xg0 + ((size_t)(n * Tc + tf)  * Bc) * H4;
                a.pre[1] = p_xg0 + (size_t)NTB * H4 + ((size_t)(n * Tc + tbk) * Bc) * H4;
                a.h_in[0]  = p_sh + (0 * 2 + par[0]) * SL;
                a.h_out[0] = p_sh + (0 * 2 + (par[0] ^ 1)) * SL;
                a.h_in[1]  = p_sh + (1 * 2 + par[1]) * SL;
                a.h_out[1] = p_sh + (1 * 2 + (par[1] ^ 1)) * SL;
                a.c[0] = p_sc + 0 * SL;
                a.c[1] = p_sc + 1 * SL;
                a.out[0] = p_x1 + (size_t)tf  * Bc * H2;        // of -> x1[:, :512]
                a.out[1] = p_x1 + (size_t)tbk * Bc * H2 + Hc;   // ob -> x1[:, 512:]
                lstm_step<<<dim3(64, 1, 2), 512>>>(a);
                par[0] ^= 1; par[1] ^= 1;
            }
            // ---- layer 1 (slots 2=fwd, 3=bwd), Wih folded in ----
            for (int s = 0; s < L; s++) {
                int tf = s, tbk = L - 1 - s;
                StepArgs a = {};
                a.layer1 = 1;
                a.out_stride = H2;
                a.Whh[0] = p_WhhT + 2 * (size_t)H4 * Hc;
                a.Whh[1] = p_WhhT + 3 * (size_t)H4 * Hc;
                a.Wih[0] = p_WihT + 0 * (size_t)H4 * H2;
                a.Wih[1] = p_WihT + 1 * (size_t)H4 * H2;
                a.bias[0] = b1f;
                a.bias[1] = b1b;
                a.xin[0] = p_x1 + (size_t)tf  * Bc * H2;
                a.xin[1] = p_x1 + (size_t)tbk * Bc * H2;
                a.h_in[0]  = p_sh + (2 * 2 + par[2]) * SL;
                a.h_out[0] = p_sh + (2 * 2 + (par[2] ^ 1)) * SL;
                a.h_in[1]  = p_sh + (3 * 2 + par[3]) * SL;
                a.h_out[1] = p_sh + (3 * 2 + (par[3] ^ 1)) * SL;
                a.c[0] = p_sc + 2 * SL;
                a.c[1] = p_sc + 3 * SL;
                a.out[0] = p_out1 + (size_t)(n * Tc + tf)  * Bc * H2;        // o1f
                a.out[1] = p_out1 + (size_t)(n * Tc + tbk) * Bc * H2 + Hc;   // o1b
                lstm_step<<<dim3(64, 1, 2), 512>>>(a);
                par[2] ^= 1; par[3] ^= 1;
            }
        }
    }

    // final FC: out[800, 30000] = g_out1 @ Wfc + bfc
    sgemm_kernel<<<dim3((Vc + 63)/64, (NTB + 63)/64), 256>>>(p_out1, Wfc, bfc, outp, NTB, Vc, H2, 0);
}

// round 2
// speedup vs baseline: 1.0006x; 1.0006x over previous
#include <cuda_runtime.h>
#include <math.h>

// Problem constants
#define Bc 16
#define Nc 5
#define Tc 10
#define Hc 512
#define Ec 250
#define Vc 30000
#define Fc 2048
#define H4 2048
#define H2 1024
#define NTB (Nc*Tc*Bc)   // 800

// ---------------- device scratch (no cudaMalloc allowed) ----------------
__device__ float g_tmp[Bc*H2];            // MLP intermediate
__device__ float g_h0[Bc*Hc];             // image h
__device__ float g_c0[Bc*Hc];             // image c
__device__ float g_sh[4*2*Bc*Hc];         // state h, 4 slots x 2 parity
__device__ float g_sc[4*Bc*Hc];           // state c, 4 slots (in-place safe)
__device__ float g_x0[NTB*Ec];            // gathered embeddings (n,t,b,e)
__device__ float g_xg0[2*NTB*H4];         // precomputed layer0 gates (+bias), per dir
__device__ float g_x1[Tc*Bc*H2];          // layer0 outputs concat [of|ob], time-indexed
__device__ float g_out1[NTB*H2];          // layer1 outputs (n,tau,b,[o1f|o1b])
__device__ float g_WhhT[4*H4*Hc];         // transposed Whh: 0=0f 1=0b 2=1f 3=1b  [2048][512]
__device__ float g_WihT[2*H4*H2];         // transposed Wih1: 0=f 1=b              [2048][1024]

// ---------------- generic fp32 GEMM: C = A[MxK] @ W[KxN] + bias (opt relu) ----------------
__global__ __launch_bounds__(256) void sgemm_kernel(
    const float* __restrict__ A, const float* __restrict__ W,
    const float* __restrict__ bias, float* __restrict__ C,
    int M, int N, int K, int relu)
{
    __shared__ float As[16][64];
    __shared__ float Bs[16][64];
    int bm = blockIdx.y * 64, bn = blockIdx.x * 64;
    int tid = threadIdx.x;
    int tm = (tid >> 4) << 2;
    int tn = (tid & 15) << 2;
    float acc[4][4] = {};
    for (int k0 = 0; k0 < K; k0 += 16) {
        #pragma unroll
        for (int e = 0; e < 4; e++) {
            int idx = tid + e * 256;
            int r = idx >> 4, c = idx & 15;
            int gr = bm + r, gc = k0 + c;
            float v = 0.f;
            if (gr < M && gc < K) v = A[(size_t)gr * K + gc];
            As[c][r] = v;
        }
        #pragma unroll
        for (int e = 0; e < 4; e++) {
            int idx = tid + e * 256;
            int r = idx >> 6, c = idx & 63;
            int gr = k0 + r, gc = bn + c;
            float v = 0.f;
            if (gr < K && gc < N) v = W[(size_t)gr * N + gc];
            Bs[r][c] = v;
        }
        __syncthreads();
        #pragma unroll
        for (int kk = 0; kk < 16; kk++) {
            float4 a4 = *(const float4*)&As[kk][tm];
            float4 b4 = *(const float4*)&Bs[kk][tn];
            float a[4] = {a4.x, a4.y, a4.z, a4.w};
            float b[4] = {b4.x, b4.y, b4.z, b4.w};
            #pragma unroll
            for (int i = 0; i < 4; i++)
                #pragma unroll
                for (int j = 0; j < 4; j++)
                    acc[i][j] = fmaf(a[i], b[j], acc[i][j]);
        }
        __syncthreads();
    }
    #pragma unroll
    for (int i = 0; i < 4; i++) {
        int gm = bm + tm + i;
        if (gm >= M) continue;
        #pragma unroll
        for (int j = 0; j < 4; j++) {
            int gn = bn + tn + j;
            if (gn >= N) continue;
            float v = acc[i][j] + bias[gn];
            if (relu) v = fmaxf(v, 0.f);
            C[(size_t)gm * N + gn] = v;
        }
    }
}

// ---------------- transpose: out[C][R] = in[R][C] ----------------
__global__ void transpose_k(const float* __restrict__ in, float* __restrict__ out, int R, int C)
{
    __shared__ float tile[32][33];
    int c0 = blockIdx.x * 32, r0 = blockIdx.y * 32;
    for (int j = threadIdx.y; j < 32; j += 8) {
        int r = r0 + j, c = c0 + threadIdx.x;
        tile[j][threadIdx.x] = (r < R && c < C) ? in[(size_t)r * C + c] : 0.f;
    }
    __syncthreads();
    for (int j = threadIdx.y; j < 32; j += 8) {
        int c = c0 + j, r = r0 + threadIdx.x;
        if (c < C && r < R) out[(size_t)c * R + r] = tile[threadIdx.x][j];
    }
}

// ---------------- embedding gather: g_x0[(n*T+t)*B+b][e] = emb[caps[b][n][t]][e] ----------------
__global__ void gather_k(const int* __restrict__ caps, const float* __restrict__ emb)
{
    int rid = blockIdx.x;          // 0..799
    int b = rid & 15;
    int nt = rid >> 4;             // n*10 + t
    int n = nt / Tc, t = nt % Tc;
    int tok = caps[b * (Nc * Tc) + n * Tc + t];
    const float* e = emb + (size_t)tok * Ec;
    float* o = g_x0 + (size_t)rid * Ec;
    for (int i = threadIdx.x; i < Ec; i += blockDim.x) o[i] = e[i];
}

// ---------------- broadcast image h/c into the 4 state slots (parity 0) ----------------
__global__ void bcast_state_k()
{
    int i = blockIdx.x * blockDim.x + threadIdx.x;
    if (i < Bc * Hc) {
        float h = g_h0[i], c = g_c0[i];
        #pragma unroll
        for (int s = 0; s < 4; s++) {
            g_sh[(s * 2 + 0) * (Bc * Hc) + i] = h;
            g_sc[s * (Bc * Hc) + i] = c;
        }
    }
}

// ---------------- one LSTM timestep, both directions (blockIdx.z = dir) ----------------
struct StepArgs {
    const float* Whh[2];    // transposed [2048][512]
    const float* pre[2];    // layer0: precomputed gates (B x 2048); layer1: unused
    const float* Wih[2];    // layer1: transposed [2048][1024]
    const float* bias[2];   // layer1 bias (2048)
    const float* xin[2];    // layer1 input rows (B x 1024)
    const float* h_in[2];
    float*       h_out[2];
    float*       c[2];      // in-place (owner-thread only)
    float*       out[2];    // h output location (per-batch stride out_stride, + dir col offset baked in)
    int out_stride;
    int layer1;
};

__global__ __launch_bounds__(512) void lstm_step(StepArgs a)
{
    int d   = blockIdx.z;
    int tid = threadIdx.x;          // 512 threads: 16 b x 8 k x 4 r-splits
    int b   = tid & 15;
    int kl  = (tid >> 4) & 7;
    int rs  = tid >> 7;             // 0..3
    int k   = blockIdx.x * 8 + kl;  // 0..511

    float acc0 = 0.f, acc1 = 0.f, acc2 = 0.f, acc3 = 0.f;

    // recurrent part: h (512) @ WhhT columns, r-chunk of 128
    {
        const float* Wt = a.Whh[d];
        const float4* h4 = (const float4*)(a.h_in[d] + b * Hc + rs * 128);
        const float4* w0 = (const float4*)(Wt + (size_t)(k)        * Hc + rs * 128);
        const float4* w1 = (const float4*)(Wt + (size_t)(k + 512)  * Hc + rs * 128);
        const float4* w2 = (const float4*)(Wt + (size_t)(k + 1024) * Hc + rs * 128);
        const float4* w3 = (const float4*)(Wt + (size_t)(k + 1536) * Hc + rs * 128);
        #pragma unroll 8
        for (int i = 0; i < 32; i++) {
            float4 h = h4[i];
            float4 w;
            w = w0[i]; acc0 += h.x*w.x + h.y*w.y + h.z*w.z + h.w*w.w;
            w = w1[i]; acc1 += h.x*w.x + h.y*w.y + h.z*w.z + h.w*w.w;
            w = w2[i]; acc2 += h.x*w.x + h.y*w.y + h.z*w.z + h.w*w.w;
            w = w3[i]; acc3 += h.x*w.x + h.y*w.y + h.z*w.z + h.w*w.w;
        }
    }
    // layer1: fold x1 (1024) @ WihT, r-chunk of 256
    if (a.layer1) {
        const float* Wt = a.Wih[d];
        const float4* x4 = (const float4*)(a.xin[d] + b * H2 + rs * 256);
        const float4* w0 = (const float4*)(Wt + (size_t)(k)        * H2 + rs * 256);
        const float4* w1 = (const float4*)(Wt + (size_t)(k + 512)  * H2 + rs * 256);
        const float4* w2 = (const float4*)(Wt + (size_t)(k + 1024) * H2 + rs * 256);
        const float4* w3 = (const float4*)(Wt + (size_t)(k + 1536) * H2 + rs * 256);
        #pragma unroll 8
        for (int i = 0; i < 64; i++) {
            float4 x = x4[i];
            float4 w;
            w = w0[i]; acc0 += x.x*w.x + x.y*w.y + x.z*w.z + x.w*w.w;
            w = w1[i]; acc1 += x.x*w.x + x.y*w.y + x.z*w.z + x.w*w.w;
            w = w2[i]; acc2 += x.x*w.x + x.y*w.y + x.z*w.z + x.w*w.w;
            w = w3[i]; acc3 += x.x*w.x + x.y*w.y + x.z*w.z + x.w*w.w;
        }
    }

    __shared__ float red[4][128][4];
    int pair = tid & 127;
    if (rs) {
        red[rs][pair][0] = acc0; red[rs][pair][1] = acc1;
        red[rs][pair][2] = acc2; red[rs][pair][3] = acc3;
    }
    __syncthreads();
    if (rs == 0) {
        acc0 += red[1][pair][0] + red[2][pair][0] + red[3][pair][0];
        acc1 += red[1][pair][1] + red[2][pair][1] + red[3][pair][1];
        acc2 += red[1][pair][2] + red[2][pair][2] + red[3][pair][2];
        acc3 += red[1][pair][3] + red[2][pair][3] + red[3][pair][3];
        float pi, pf, pg, po;
        if (a.layer1) {
            const float* bs = a.bias[d];
            pi = bs[k]; pf = bs[k + 512]; pg = bs[k + 1024]; po = bs[k + 1536];
        } else {
            const float* xg = a.pre[d] + (size_t)b * H4;
            pi = xg[k]; pf = xg[k + 512]; pg = xg[k + 1024]; po = xg[k + 1536];
        }
        float gi = acc0 + pi, gf = acc1 + pf, gg = acc2 + pg, go = acc3 + po;
        float si = 1.f / (1.f + expf(-gi));
        float sf = 1.f / (1.f + expf(-gf));
        float so = 1.f / (1.f + expf(-go));
        int idx = b * Hc + k;
        float cn = sf * a.c[d][idx] + si * tanhf(gg);
        float hn = so * tanhf(cn);
        a.c[d][idx]     = cn;
        a.h_out[d][idx] = hn;
        a.out[d][b * a.out_stride + k] = hn;
    }
}

// ---------------- host ----------------
extern "C" void kernel_launch(void* const* d_in, const int* in_sizes, int n_in,
                              void* d_out, int out_size)
{
    const float* img   = (const float*)d_in[0];
    const int*   caps  = (const int*)  d_in[1];
    const float* Wh1   = (const float*)d_in[2];
    const float* bh1   = (const float*)d_in[3];
    const float* Wh2   = (const float*)d_in[4];
    const float* bh2   = (const float*)d_in[5];
    const float* Wc1   = (const float*)d_in[6];
    const float* bc1   = (const float*)d_in[7];
    const float* Wc2   = (const float*)d_in[8];
    const float* bc2   = (const float*)d_in[9];
    const float* emb   = (const float*)d_in[10];
    const float* Wih0f = (const float*)d_in[11];
    const float* Whh0f = (const float*)d_in[12];
    const float* b0f   = (const float*)d_in[13];
    const float* Wih0b = (const float*)d_in[14];
    const float* Whh0b = (const float*)d_in[15];
    const float* b0b   = (const float*)d_in[16];
    const float* Wih1f = (const float*)d_in[17];
    const float* Whh1f = (const float*)d_in[18];
    const float* b1f   = (const float*)d_in[19];
    const float* Wih1b = (const float*)d_in[20];
    const float* Whh1b = (const float*)d_in[21];
    const float* b1b   = (const float*)d_in[22];
    const float* Wfc   = (const float*)d_in[23];
    const float* bfc   = (const float*)d_in[24];
    float* outp = (float*)d_out;

    // resolve scratch symbol addresses (pure queries; capture-safe)
    float *p_tmp, *p_h0, *p_c0, *p_x0, *p_xg0, *p_x1, *p_out1, *p_sh, *p_sc, *p_WhhT, *p_WihT;
    cudaGetSymbolAddress((void**)&p_tmp,  g_tmp);
    cudaGetSymbolAddress((void**)&p_h0,   g_h0);
    cudaGetSymbolAddress((void**)&p_c0,   g_c0);
    cudaGetSymbolAddress((void**)&p_x0,   g_x0);
    cudaGetSymbolAddress((void**)&p_xg0,  g_xg0);
    cudaGetSymbolAddress((void**)&p_x1,   g_x1);
    cudaGetSymbolAddress((void**)&p_out1, g_out1);
    cudaGetSymbolAddress((void**)&p_sh,   g_sh);
    cudaGetSymbolAddress((void**)&p_sc,   g_sc);
    cudaGetSymbolAddress((void**)&p_WhhT, g_WhhT);
    cudaGetSymbolAddress((void**)&p_WihT, g_WihT);

    const int SL = Bc * Hc;  // state slot size

    dim3 tb(32, 8);
    // transpose recurrent / layer1-input weights (needed every launch; cheap)
    transpose_k<<<dim3(H4/32, Hc/32), tb>>>(Whh0f, p_WhhT + 0 * (size_t)H4 * Hc, Hc, H4);
    transpose_k<<<dim3(H4/32, Hc/32), tb>>>(Whh0b, p_WhhT + 1 * (size_t)H4 * Hc, Hc, H4);
    transpose_k<<<dim3(H4/32, Hc/32), tb>>>(Whh1f, p_WhhT + 2 * (size_t)H4 * Hc, Hc, H4);
    transpose_k<<<dim3(H4/32, Hc/32), tb>>>(Whh1b, p_WhhT + 3 * (size_t)H4 * Hc, Hc, H4);
    transpose_k<<<dim3(H4/32, H2/32), tb>>>(Wih1f, p_WihT + 0 * (size_t)H4 * H2, H2, H4);
    transpose_k<<<dim3(H4/32, H2/32), tb>>>(Wih1b, p_WihT + 1 * (size_t)H4 * H2, H2, H4);

    // image MLPs: h then c (g_tmp reuse is stream-ordered)
    sgemm_kernel<<<dim3(H2/64, 1), 256>>>(img,   Wh1, bh1, p_tmp, Bc, H2, Fc, 1);
    sgemm_kernel<<<dim3(Hc/64, 1), 256>>>(p_tmp, Wh2, bh2, p_h0,  Bc, Hc, H2, 1);
    sgemm_kernel<<<dim3(H2/64, 1), 256>>>(img,   Wc1, bc1, p_tmp, Bc, H2, Fc, 1);
    sgemm_kernel<<<dim3(Hc/64, 1), 256>>>(p_tmp, Wc2, bc2, p_c0,  Bc, Hc, H2, 1);
    bcast_state_k<<<(Bc*Hc + 255)/256, 256>>>();

    // embeddings + layer0 input gates (reused by ALL 50 calls)
    gather_k<<<NTB, 256>>>(caps, emb);
    sgemm_kernel<<<dim3(H4/64, (NTB+63)/64), 256>>>(p_x0, Wih0f, b0f, p_xg0,                      NTB, H4, Ec, 0);
    sgemm_kernel<<<dim3(H4/64, (NTB+63)/64), 256>>>(p_x0, Wih0b, b0b, p_xg0 + (size_t)NTB * H4,   NTB, H4, Ec, 0);

    // sequential bilstm2 chain
    int par[4] = {0, 0, 0, 0};
    for (int t = 0; t < Tc; t++) {
        for (int n = 0; n < Nc; n++) {
            int L = t + 1;
            // ---- layer 0 (slots 0=fwd, 1=bwd) ----
            for (int s = 0; s < L; s++) {
                int tf = s, tbk = L - 1 - s;
                StepArgs a = {};
                a.layer1 = 0;
                a.out_stride = H2;
                a.Whh[0] = p_WhhT + 0 * (size_t)H4 * Hc;
                a.Whh[1] = p_WhhT + 1 * (size_t)H4 * Hc;
                a.pre[0] = p_xg0 + ((size_t)(n * Tc + tf)  * Bc) * H4;
                a.pre[1] = p_xg0 + (size_t)NTB * H4 + ((size_t)(n * Tc + tbk) * Bc) * H4;
                a.h_in[0]  = p_sh + (0 * 2 + par[0]) * SL;
                a.h_out[0] = p_sh + (0 * 2 + (par[0] ^ 1)) * SL;
                a.h_in[1]  = p_sh + (1 * 2 + par[1]) * SL;
                a.h_out[1] = p_sh + (1 * 2 + (par[1] ^ 1)) * SL;
                a.c[0] = p_sc + 0 * SL;
                a.c[1] = p_sc + 1 * SL;
                a.out[0] = p_x1 + (size_t)tf  * Bc * H2;        // of -> x1[:, :512]
                a.out[1] = p_x1 + (size_t)tbk * Bc * H2 + Hc;   // ob -> x1[:, 512:]
                lstm_step<<<dim3(64, 1, 2), 512>>>(a);
                par[0] ^= 1; par[1] ^= 1;
            }
            // ---- layer 1 (slots 2=fwd, 3=bwd), Wih folded in ----
            for (int s = 0; s < L; s++) {
                int tf = s, tbk = L - 1 - s;
                StepArgs a = {};
                a.layer1 = 1;
                a.out_stride = H2;
                a.Whh[0] = p_WhhT + 2 * (size_t)H4 * Hc;
                a.Whh[1] = p_WhhT + 3 * (size_t)H4 * Hc;
                a.Wih[0] = p_WihT + 0 * (size_t)H4 * H2;
                a.Wih[1] = p_WihT + 1 * (size_t)H4 * H2;
                a.bias[0] = b1f;
                a.bias[1] = b1b;
                a.xin[0] = p_x1 + (size_t)tf  * Bc * H2;
                a.xin[1] = p_x1 + (size_t)tbk * Bc * H2;
                a.h_in[0]  = p_sh + (2 * 2 + par[2]) * SL;
                a.h_out[0] = p_sh + (2 * 2 + (par[2] ^ 1)) * SL;
                a.h_in[1]  = p_sh + (3 * 2 + par[3]) * SL;
                a.h_out[1] = p_sh + (3 * 2 + (par[3] ^ 1)) * SL;
                a.c[0] = p_sc + 2 * SL;
                a.c[1] = p_sc + 3 * SL;
                a.out[0] = p_out1 + (size_t)(n * Tc + tf)  * Bc * H2;        // o1f
                a.out[1] = p_out1 + (size_t)(n * Tc + tbk) * Bc * H2 + Hc;   // o1b
                lstm_step<<<dim3(64, 1, 2), 512>>>(a);
                par[2] ^= 1; par[3] ^= 1;
            }
        }
    }

    // final FC: out[800, 30000] = g_out1 @ Wfc + bfc
    sgemm_kernel<<<dim3((Vc + 63)/64, (NTB + 63)/64), 256>>>(p_out1, Wfc, bfc, outp, NTB, Vc, H2, 0);
}

// round 4
// speedup vs baseline: 1.0488x; 1.0481x over previous
#include <cuda_runtime.h>
#include <math.h>

// Problem constants
#define Bc 16
#define Nc 5
#define Tc 10
#define Hc 512
#define Ec 250
#define Vc 30000
#define Fc 2048
#define H4 2048
#define H2 1024
#define NTB (Nc*Tc*Bc)   // 800

// packed fp32x2 FMA (SASS FFMA2) — d += a*b lane-wise on packed pairs
#define FMA2(d, a, b) asm("fma.rn.f32x2 %0, %1, %2, %0;" : "+l"(d) : "l"(a), "l"(b))

__device__ __forceinline__ float f2lo(unsigned long long v) { return __uint_as_float((unsigned)v); }
__device__ __forceinline__ float f2hi(unsigned long long v) { return __uint_as_float((unsigned)(v >> 32)); }

// ---------------- device scratch (no cudaMalloc allowed) ----------------
__device__ __align__(16) float g_tmp[Bc*H2];            // MLP intermediate
__device__ __align__(16) float g_h0[Bc*Hc];             // image h
__device__ __align__(16) float g_c0[Bc*Hc];             // image c
__device__ __align__(16) float g_sh[4*2*Bc*Hc];         // state h, 4 slots x 2 parity
__device__ __align__(16) float g_sc[4*Bc*Hc];           // state c, 4 slots
__device__ __align__(16) float g_x0[NTB*Ec];            // gathered embeddings
__device__ __align__(16) float g_xg0[2*NTB*H4];         // precomputed layer0 gates (+bias), per dir
__device__ __align__(16) float g_x1[Tc*Bc*H2];          // layer0 outputs concat [of|ob]
__device__ __align__(16) float g_out1[NTB*H2];          // layer1 outputs
__device__ __align__(16) float g_WhhT[4*H4*Hc];         // transposed Whh: 0=0f 1=0b 2=1f 3=1b
__device__ __align__(16) float g_WihT[2*H4*H2];         // transposed Wih1: 0=f 1=b

// ================= small fp32 GEMM (tiny image MLPs) =================
__global__ __launch_bounds__(256) void sgemm_kernel(
    const float* __restrict__ A, const float* __restrict__ W,
    const float* __restrict__ bias, float* __restrict__ C,
    int M, int N, int K, int relu)
{
    __shared__ float As[16][64];
    __shared__ float Bs[16][64];
    int bm = blockIdx.y * 64, bn = blockIdx.x * 64;
    int tid = threadIdx.x;
    int tm = (tid >> 4) << 2;
    int tn = (tid & 15) << 2;
    float acc[4][4] = {};
    for (int k0 = 0; k0 < K; k0 += 16) {
        #pragma unroll
        for (int e = 0; e < 4; e++) {
            int idx = tid + e * 256;
            int r = idx >> 4, c = idx & 15;
            int gr = bm + r, gc = k0 + c;
            float v = 0.f;
            if (gr < M && gc < K) v = A[(size_t)gr * K + gc];
            As[c][r] = v;
        }
        #pragma unroll
        for (int e = 0; e < 4; e++) {
            int idx = tid + e * 256;
            int r = idx >> 6, c = idx & 63;
            int gr = k0 + r, gc = bn + c;
            float v = 0.f;
            if (gr < K && gc < N) v = W[(size_t)gr * N + gc];
            Bs[r][c] = v;
        }
        __syncthreads();
        #pragma unroll
        for (int kk = 0; kk < 16; kk++) {
            float4 a4 = *(const float4*)&As[kk][tm];
            float4 b4 = *(const float4*)&Bs[kk][tn];
            float a[4] = {a4.x, a4.y, a4.z, a4.w};
            float b[4] = {b4.x, b4.y, b4.z, b4.w};
            #pragma unroll
            for (int i = 0; i < 4; i++)
                #pragma unroll
                for (int j = 0; j < 4; j++)
                    acc[i][j] = fmaf(a[i], b[j], acc[i][j]);
        }
        __syncthreads();
    }
    #pragma unroll
    for (int i = 0; i < 4; i++) {
        int gm = bm + tm + i;
        if (gm >= M) continue;
        #pragma unroll
        for (int j = 0; j < 4; j++) {
            int gn = bn + tn + j;
            if (gn >= N) continue;
            float v = acc[i][j] + bias[gn];
            if (relu) v = fmaxf(v, 0.f);
            C[(size_t)gm * N + gn] = v;
        }
    }
}

// ================= big GEMM: 128x128 tile, 8x8 micro-tile, f32x2 FMA =================
// C[M,N] = A[M,K] @ B[K,N] + bias
__global__ __launch_bounds__(256, 2) void gemm128(
    const float* __restrict__ A, const float* __restrict__ B,
    const float* __restrict__ bias, float* __restrict__ C,
    int M, int N, int K)
{
    __shared__ __align__(16) float As[2][16][128];
    __shared__ __align__(16) float Bs[2][16][256];   // duplicated pairs

    int tid = threadIdx.x;
    int bm = blockIdx.y * 128, bn = blockIdx.x * 128;
    int tx = tid & 15, ty = tid >> 4;
    int ar = tid >> 2, ac = (tid & 3) * 4;
    int br = tid >> 5, bc = (tid & 31) * 4;

    bool fullM = (bm + 128 <= M);
    bool fullN = (bn + 128 <= N);
    bool alnA  = ((K & 3) == 0);   // K=250 rows break float4 alignment

    unsigned long long acc[4][8];
    #pragma unroll
    for (int i = 0; i < 4; i++)
        #pragma unroll
        for (int j = 0; j < 8; j++) acc[i][j] = 0ull;

    float a0[4], a1[4], b0[4], b1[4];
    int KT = (K + 15) / 16;

#define LOADTILE(KT_) do {                                                        \
    int k0 = (KT_) * 16;                                                          \
    bool fk = (k0 + 16 <= K);                                                     \
    if (fk && fullM && alnA) {                                                    \
        float4 r0 = *(const float4*)&A[(size_t)(bm + ar) * K + k0 + ac];          \
        float4 r1 = *(const float4*)&A[(size_t)(bm + ar + 64) * K + k0 + ac];     \
        a0[0]=r0.x; a0[1]=r0.y; a0[2]=r0.z; a0[3]=r0.w;                           \
        a1[0]=r1.x; a1[1]=r1.y; a1[2]=r1.z; a1[3]=r1.w;                           \
    } else {                                                                      \
        int gr0 = bm + ar, gr1 = bm + ar + 64;                                    \
        _Pragma("unroll") for (int j = 0; j < 4; j++) {                           \
            int gk = k0 + ac + j;                                                 \
            bool ok = (gk < K);                                                   \
            a0[j] = (ok && gr0 < M) ? A[(size_t)gr0 * K + gk] : 0.f;              \
            a1[j] = (ok && gr1 < M) ? A[(size_t)gr1 * K + gk] : 0.f;              \
        }                                                                         \
    }                                                                             \
    if (fk && fullN) {                                                            \
        float4 r0 = *(const float4*)&B[(size_t)(k0 + br) * N + bn + bc];          \
        float4 r1 = *(const float4*)&B[(size_t)(k0 + br + 8) * N + bn + bc];      \
        b0[0]=r0.x; b0[1]=r0.y; b0[2]=r0.z; b0[3]=r0.w;                           \
        b1[0]=r1.x; b1[1]=r1.y; b1[2]=r1.z; b1[3]=r1.w;                           \
    } else {                                                                      \
        int gk0 = k0 + br, gk1 = k0 + br + 8;                                     \
        _Pragma("unroll") for (int j = 0; j < 4; j++) {                           \
            int gc = bn + bc + j;                                                 \
            bool ok = (gc < N);                                                   \
            b0[j] = (ok && gk0 < K) ? B[(size_t)gk0 * N + gc] : 0.f;              \
            b1[j] = (ok && gk1 < K) ? B[(size_t)gk1 * N + gc] : 0.f;              \
        }                                                                         \
    }                                                                             \
} while (0)

#define STORETILE(BUF_) do {                                                      \
    _Pragma("unroll") for (int j = 0; j < 4; j++) {                               \
        As[BUF_][ac + j][ar]      = a0[j];                                        \
        As[BUF_][ac + j][ar + 64] = a1[j];                                        \
        Bs[BUF_][br][(bc + j) * 2]         = b0[j];                               \
        Bs[BUF_][br][(bc + j) * 2 + 1]     = b0[j];                               \
        Bs[BUF_][br + 8][(bc + j) * 2]     = b1[j];                               \
        Bs[BUF_][br + 8][(bc + j) * 2 + 1] = b1[j];                               \
    }                                                                             \
} while (0)

    LOADTILE(0);
    STORETILE(0);
    __syncthreads();

    for (int kt = 0; kt < KT; kt++) {
        int cur = kt & 1;
        if (kt + 1 < KT) LOADTILE(kt + 1);
        #pragma unroll
        for (int k = 0; k < 16; k++) {
            unsigned long long a2[4], b2[8];
            #pragma unroll
            for (int i = 0; i < 4; i++)
                a2[i] = *(const unsigned long long*)&As[cur][k][ty * 8 + 2 * i];
            #pragma unroll
            for (int j = 0; j < 8; j++)
                b2[j] = *(const unsigned long long*)&Bs[cur][k][(tx + 16 * j) * 2];
            #pragma unroll
            for (int i = 0; i < 4; i++)
                #pragma unroll
                for (int j = 0; j < 8; j++)
                    FMA2(acc[i][j], a2[i], b2[j]);
        }
        if (kt + 1 < KT) STORETILE(cur ^ 1);
        __syncthreads();
    }

    // epilogue
    #pragma unroll
    for (int j = 0; j < 8; j++) {
        int col = bn + tx + 16 * j;
        if (col >= N) continue;
        float bb = bias[col];
        #pragma unroll
        for (int i = 0; i < 4; i++) {
            int r0 = bm + ty * 8 + 2 * i;
            float lo = f2lo(acc[i][j]) + bb;
            float hi = f2hi(acc[i][j]) + bb;
            if (r0 < M)     C[(size_t)r0 * N + col] = lo;
            if (r0 + 1 < M) C[(size_t)(r0 + 1) * N + col] = hi;
        }
    }
#undef LOADTILE
#undef STORETILE
}

// ---------------- transpose: out[C][R] = in[R][C] ----------------
__global__ void transpose_k(const float* __restrict__ in, float* __restrict__ out, int R, int C)
{
    __shared__ float tile[32][33];
    int c0 = blockIdx.x * 32, r0 = blockIdx.y * 32;
    for (int j = threadIdx.y; j < 32; j += 8) {
        int r = r0 + j, c = c0 + threadIdx.x;
        tile[j][threadIdx.x] = (r < R && c < C) ? in[(size_t)r * C + c] : 0.f;
    }
    __syncthreads();
    for (int j = threadIdx.y; j < 32; j += 8) {
        int c = c0 + j, r = r0 + threadIdx.x;
        if (c < C && r < R) out[(size_t)c * R + r] = tile[threadIdx.x][j];
    }
}

// ---------------- embedding gather ----------------
__global__ void gather_k(const int* __restrict__ caps, const float* __restrict__ emb)
{
    int rid = blockIdx.x;          // 0..799
    int b = rid & 15;
    int nt = rid >> 4;             // n*10 + t
    int n = nt / Tc, t = nt % Tc;
    int tok = caps[b * (Nc * Tc) + n * Tc + t];
    const float* e = emb + (size_t)tok * Ec;
    float* o = g_x0 + (size_t)rid * Ec;
    for (int i = threadIdx.x; i < Ec; i += blockDim.x) o[i] = e[i];
}

// ---------------- broadcast image h/c into the 4 state slots (parity 0) ----------------
__global__ void bcast_state_k()
{
    int i = blockIdx.x * blockDim.x + threadIdx.x;
    if (i < Bc * Hc) {
        float h = g_h0[i], c = g_c0[i];
        #pragma unroll
        for (int s = 0; s < 4; s++) {
            g_sh[(s * 2 + 0) * (Bc * Hc) + i] = h;
            g_sc[s * (Bc * Hc) + i] = c;
        }
    }
}

// ---------------- one LSTM timestep, both directions (blockIdx.z = dir) ----------------
struct StepArgs {
    const float* Whh[2];    // transposed [2048][512]
    const float* pre[2];    // layer0: precomputed gates (B x 2048)
    const float* Wih[2];    // layer1: transposed [2048][1024]
    const float* bias[2];   // layer1 bias (2048)
    const float* xin[2];    // layer1 input rows (B x 1024)
    const float* h_in[2];
    float*       h_out[2];
    float*       c[2];
    float*       out[2];
    int out_stride;
    int layer1;
};

__global__ __launch_bounds__(512) void lstm_step(StepArgs a)
{
    int d   = blockIdx.z;
    int tid = threadIdx.x;          // 512 threads: 16 b x 8 k x 4 r-splits
    int b   = tid & 15;
    int kl  = (tid >> 4) & 7;
    int rs  = tid >> 7;             // 0..3
    int k   = blockIdx.x * 8 + kl;  // 0..511

    unsigned long long A0 = 0ull, A1 = 0ull, A2 = 0ull, A3 = 0ull;

    // recurrent part: h (512) @ WhhT columns, r-chunk of 128 floats
    {
        const float* Wt = a.Whh[d];
        const ulonglong2* h4 = (const ulonglong2*)(a.h_in[d] + b * Hc + rs * 128);
        const ulonglong2* w0 = (const ulonglong2*)(Wt + (size_t)(k)        * Hc + rs * 128);
        const ulonglong2* w1 = (const ulonglong2*)(Wt + (size_t)(k + 512)  * Hc + rs * 128);
        const ulonglong2* w2 = (const ulonglong2*)(Wt + (size_t)(k + 1024) * Hc + rs * 128);
        const ulonglong2* w3 = (const ulonglong2*)(Wt + (size_t)(k + 1536) * Hc + rs * 128);
        #pragma unroll 8
        for (int i = 0; i < 32; i++) {
            ulonglong2 h = h4[i];
            ulonglong2 w;
            w = w0[i]; FMA2(A0, h.x, w.x); FMA2(A0, h.y, w.y);
            w = w1[i]; FMA2(A1, h.x, w.x); FMA2(A1, h.y, w.y);
            w = w2[i]; FMA2(A2, h.x, w.x); FMA2(A2, h.y, w.y);
            w = w3[i]; FMA2(A3, h.x, w.x); FMA2(A3, h.y, w.y);
        }
    }
    // layer1: fold x1 (1024) @ WihT, r-chunk of 256 floats
    if (a.layer1) {
        const float* Wt = a.Wih[d];
        const ulonglong2* x4 = (const ulonglong2*)(a.xin[d] + b * H2 + rs * 256);
        const ulonglong2* w0 = (const ulonglong2*)(Wt + (size_t)(k)        * H2 + rs * 256);
        const ulonglong2* w1 = (const ulonglong2*)(Wt + (size_t)(k + 512)  * H2 + rs * 256);
        const ulonglong2* w2 = (const ulonglong2*)(Wt + (size_t)(k + 1024) * H2 + rs * 256);
        const ulonglong2* w3 = (const ulonglong2*)(Wt + (size_t)(k + 1536) * H2 + rs * 256);
        #pragma unroll 8
        for (int i = 0; i < 64; i++) {
            ulonglong2 x = x4[i];
            ulonglong2 w;
            w = w0[i]; FMA2(A0, x.x, w.x); FMA2(A0, x.y, w.y);
            w = w1[i]; FMA2(A1, x.x, w.x); FMA2(A1, x.y, w.y);
            w = w2[i]; FMA2(A2, x.x, w.x); FMA2(A2, x.y, w.y);
            w = w3[i]; FMA2(A3, x.x, w.x); FMA2(A3, x.y, w.y);
        }
    }

    float acc0 = f2lo(A0) + f2hi(A0);
    float acc1 = f2lo(A1) + f2hi(A1);
    float acc2 = f2lo(A2) + f2hi(A2);
    float acc3 = f2lo(A3) + f2hi(A3);

    __shared__ float red[4][128][4];
    int pair = tid & 127;
    if (rs) {
        red[rs][pair][0] = acc0; red[rs][pair][1] = acc1;
        red[rs][pair][2] = acc2; red[rs][pair][3] = acc3;
    }
    __syncthreads();
    if (rs == 0) {
        acc0 += red[1][pair][0] + red[2][pair][0] + red[3][pair][0];
        acc1 += red[1][pair][1] + red[2][pair][1] + red[3][pair][1];
        acc2 += red[1][pair][2] + red[2][pair][2] + red[3][pair][2];
        acc3 += red[1][pair][3] + red[2][pair][3] + red[3][pair][3];
        float pi, pf, pg, po;
        if (a.layer1) {
            const float* bs = a.bias[d];
            pi = bs[k]; pf = bs[k + 512]; pg = bs[k + 1024]; po = bs[k + 1536];
        } else {
            const float* xg = a.pre[d] + (size_t)b * H4;
            pi = xg[k]; pf = xg[k + 512]; pg = xg[k + 1024]; po = xg[k + 1536];
        }
        float gi = acc0 + pi, gf = acc1 + pf, gg = acc2 + pg, go = acc3 + po;
        float si = 1.f / (1.f + expf(-gi));
        float sf = 1.f / (1.f + expf(-gf));
        float so = 1.f / (1.f + expf(-go));
        int idx = b * Hc + k;
        float cn = sf * a.c[d][idx] + si * tanhf(gg);
        float hn = so * tanhf(cn);
        a.c[d][idx]     = cn;
        a.h_out[d][idx] = hn;
        a.out[d][b * a.out_stride + k] = hn;
    }
}

// ---------------- host ----------------
extern "C" void kernel_launch(void* const* d_in, const int* in_sizes, int n_in,
                              void* d_out, int out_size)
{
    const float* img   = (const float*)d_in[0];
    const int*   caps  = (const int*)  d_in[1];
    const float* Wh1   = (const float*)d_in[2];
    const float* bh1   = (const float*)d_in[3];
    const float* Wh2   = (const float*)d_in[4];
    const float* bh2   = (const float*)d_in[5];
    const float* Wc1   = (const float*)d_in[6];
    const float* bc1   = (const float*)d_in[7];
    const float* Wc2   = (const float*)d_in[8];
    const float* bc2   = (const float*)d_in[9];
    const float* emb   = (const float*)d_in[10];
    const float* Wih0f = (const float*)d_in[11];
    const float* Whh0f = (const float*)d_in[12];
    const float* b0f   = (const float*)d_in[13];
    const float* Wih0b = (const float*)d_in[14];
    const float* Whh0b = (const float*)d_in[15];
    const float* b0b   = (const float*)d_in[16];
    const float* Wih1f = (const float*)d_in[17];
    const float* Whh1f = (const float*)d_in[18];
    const float* b1f   = (const float*)d_in[19];
    const float* Wih1b = (const float*)d_in[20];
    const float* Whh1b = (const float*)d_in[21];
    const float* b1b   = (const float*)d_in[22];
    const float* Wfc   = (const float*)d_in[23];
    const float* bfc   = (const float*)d_in[24];
    float* outp = (float*)d_out;

    float *p_tmp, *p_h0, *p_c0, *p_x0, *p_xg0, *p_x1, *p_out1, *p_sh, *p_sc, *p_WhhT, *p_WihT;
    cudaGetSymbolAddress((void**)&p_tmp,  g_tmp);
    cudaGetSymbolAddress((void**)&p_h0,   g_h0);
    cudaGetSymbolAddress((void**)&p_c0,   g_c0);
    cudaGetSymbolAddress((void**)&p_x0,   g_x0);
    cudaGetSymbolAddress((void**)&p_xg0,  g_xg0);
    cudaGetSymbolAddress((void**)&p_x1,   g_x1);
    cudaGetSymbolAddress((void**)&p_out1, g_out1);
    cudaGetSymbolAddress((void**)&p_sh,   g_sh);
    cudaGetSymbolAddress((void**)&p_sc,   g_sc);
    cudaGetSymbolAddress((void**)&p_WhhT, g_WhhT);
    cudaGetSymbolAddress((void**)&p_WihT, g_WihT);

    const int SL = Bc * Hc;

    dim3 tb(32, 8);
    transpose_k<<<dim3(H4/32, Hc/32), tb>>>(Whh0f, p_WhhT + 0 * (size_t)H4 * Hc, Hc, H4);
    transpose_k<<<dim3(H4/32, Hc/32), tb>>>(Whh0b, p_WhhT + 1 * (size_t)H4 * Hc, Hc, H4);
    transpose_k<<<dim3(H4/32, Hc/32), tb>>>(Whh1f, p_WhhT + 2 * (size_t)H4 * Hc, Hc, H4);
    transpose_k<<<dim3(H4/32, Hc/32), tb>>>(Whh1b, p_WhhT + 3 * (size_t)H4 * Hc, Hc, H4);
    transpose_k<<<dim3(H4/32, H2/32), tb>>>(Wih1f, p_WihT + 0 * (size_t)H4 * H2, H2, H4);
    transpose_k<<<dim3(H4/32, H2/32), tb>>>(Wih1b, p_WihT + 1 * (size_t)H4 * H2, H2, H4);

    // image MLPs
    sgemm_kernel<<<dim3(H2/64, 1), 256>>>(img,   Wh1, bh1, p_tmp, Bc, H2, Fc, 1);
    sgemm_kernel<<<dim3(Hc/64, 1), 256>>>(p_tmp, Wh2, bh2, p_h0,  Bc, Hc, H2, 1);
    sgemm_kernel<<<dim3(H2/64, 1), 256>>>(img,   Wc1, bc1, p_tmp, Bc, H2, Fc, 1);
    sgemm_kernel<<<dim3(Hc/64, 1), 256>>>(p_tmp, Wc2, bc2, p_c0,  Bc, Hc, H2, 1);
    bcast_state_k<<<(Bc*Hc + 255)/256, 256>>>();

    // embeddings + layer0 input gates (shared by all 50 bilstm calls)
    gather_k<<<NTB, 256>>>(caps, emb);
    gemm128<<<dim3((H4+127)/128, (NTB+127)/128), 256>>>(p_x0, Wih0f, b0f, p_xg0,                    NTB, H4, Ec);
    gemm128<<<dim3((H4+127)/128, (NTB+127)/128), 256>>>(p_x0, Wih0b, b0b, p_xg0 + (size_t)NTB * H4, NTB, H4, Ec);

    // sequential bilstm2 chain
    int par[4] = {0, 0, 0, 0};
    for (int t = 0; t < Tc; t++) {
        for (int n = 0; n < Nc; n++) {
            int L = t + 1;
            for (int s = 0; s < L; s++) {
                int tf = s, tbk = L - 1 - s;
                StepArgs a = {};
                a.layer1 = 0;
                a.out_stride = H2;
                a.Whh[0] = p_WhhT + 0 * (size_t)H4 * Hc;
                a.Whh[1] = p_WhhT + 1 * (size_t)H4 * Hc;
                a.pre[0] = p_xg0 + ((size_t)(n * Tc + tf)  * Bc) * H4;
                a.pre[1] = p_xg0 + (size_t)NTB * H4 + ((size_t)(n * Tc + tbk) * Bc) * H4;
                a.h_in[0]  = p_sh + (0 * 2 + par[0]) * SL;
                a.h_out[0] = p_sh + (0 * 2 + (par[0] ^ 1)) * SL;
                a.h_in[1]  = p_sh + (1 * 2 + par[1]) * SL;
                a.h_out[1] = p_sh + (1 * 2 + (par[1] ^ 1)) * SL;
                a.c[0] = p_sc + 0 * SL;
                a.c[1] = p_sc + 1 * SL;
                a.out[0] = p_x1 + (size_t)tf  * Bc * H2;
                a.out[1] = p_x1 + (size_t)tbk * Bc * H2 + Hc;
                lstm_step<<<dim3(64, 1, 2), 512>>>(a);
                par[0] ^= 1; par[1] ^= 1;
            }
            for (int s = 0; s < L; s++) {
                int tf = s, tbk = L - 1 - s;
                StepArgs a = {};
                a.layer1 = 1;
                a.out_stride = H2;
                a.Whh[0] = p_WhhT + 2 * (size_t)H4 * Hc;
                a.Whh[1] = p_WhhT + 3 * (size_t)H4 * Hc;
                a.Wih[0] = p_WihT + 0 * (size_t)H4 * H2;
                a.Wih[1] = p_WihT + 1 * (size_t)H4 * H2;
                a.bias[0] = b1f;
                a.bias[1] = b1b;
                a.xin[0] = p_x1 + (size_t)tf  * Bc * H2;
                a.xin[1] = p_x1 + (size_t)tbk * Bc * H2;
                a.h_in[0]  = p_sh + (2 * 2 + par[2]) * SL;
                a.h_out[0] = p_sh + (2 * 2 + (par[2] ^ 1)) * SL;
                a.h_in[1]  = p_sh + (3 * 2 + par[3]) * SL;
                a.h_out[1] = p_sh + (3 * 2 + (par[3] ^ 1)) * SL;
                a.c[0] = p_sc + 2 * SL;
                a.c[1] = p_sc + 3 * SL;
                a.out[0] = p_out1 + (size_t)(n * Tc + tf)  * Bc * H2;
                a.out[1] = p_out1 + (size_t)(n * Tc + tbk) * Bc * H2 + Hc;
                lstm_step<<<dim3(64, 1, 2), 512>>>(a);
                par[2] ^= 1; par[3] ^= 1;
            }
        }
    }

    // final FC: out[800, 30000] = g_out1 @ Wfc + bfc
    gemm128<<<dim3((Vc + 127)/128, (NTB + 127)/128), 256>>>(p_out1, Wfc, bfc, outp, NTB, Vc, H2);
}

// round 5
// speedup vs baseline: 1.7293x; 1.6489x over previous
#include <cuda_runtime.h>
#include <math.h>

// Problem constants
#define Bc 16
#define Nc 5
#define Tc 10
#define Hc 512
#define Ec 250
#define Vc 30000
#define Fc 2048
#define H4 2048
#define H2 1024
#define NTB (Nc*Tc*Bc)   // 800
#define NBLK 128
#define HSTRIDE 20       // smem row stride for hs (pad 16 -> 20 for bank spread)

// packed fp32x2 FMA (SASS FFMA2)
#define FMA2(d, a, b) asm("fma.rn.f32x2 %0, %1, %2, %0;" : "+l"(d) : "l"(a), "l"(b))

__device__ __forceinline__ float f2lo(unsigned long long v) { return __uint_as_float((unsigned)v); }
__device__ __forceinline__ float f2hi(unsigned long long v) { return __uint_as_float((unsigned)(v >> 32)); }
__device__ __forceinline__ unsigned long long splat2(float w) {
    unsigned long long d;
    asm("mov.b64 %0, {%1, %1};" : "=l"(d) : "r"(__float_as_uint(w)));
    return d;
}

// ---------------- device scratch ----------------
__device__ __align__(16) float g_tmp[Bc*H2];
__device__ __align__(16) float g_h0[Bc*Hc];
__device__ __align__(16) float g_c0[Bc*Hc];
__device__ __align__(16) float g_hst[4][2][Hc*Bc];   // state h, k-major [k][b], 4 slots x 2 parity
__device__ __align__(16) float g_cst[4][Hc*Bc];      // state c, k-major
__device__ __align__(16) float g_x0[NTB*Ec];
__device__ __align__(16) float g_xg0[2*NTB*H4];      // layer0 input gates (+bias), per dir
__device__ __align__(16) float g_x1[Tc*H2*Bc];       // layer0 outputs, k-major per t: [t][1024][16]
__device__ __align__(16) float g_out1[NTB*H2];       // layer1 outputs, row-major for FC
__device__ __align__(16) float g_W0T[2*H4*Hc];       // transposed Whh0 per dir [2048][512]
__device__ __align__(16) float g_W1T[2*H4*(Hc+H2)];  // fused [WhhT|WihT] per dir [2048][1536]

__device__ unsigned g_barcnt = 0;
__device__ unsigned g_barsense = 0;

// ================= small fp32 GEMM (tiny image MLPs) =================
__global__ __launch_bounds__(256) void sgemm_kernel(
    const float* __restrict__ A, const float* __restrict__ W,
    const float* __restrict__ bias, float* __restrict__ C,
    int M, int N, int K, int relu)
{
    __shared__ float As[16][64];
    __shared__ float Bs[16][64];
    int bm = blockIdx.y * 64, bn = blockIdx.x * 64;
    int tid = threadIdx.x;
    int tm = (tid >> 4) << 2;
    int tn = (tid & 15) << 2;
    float acc[4][4] = {};
    for (int k0 = 0; k0 < K; k0 += 16) {
        #pragma unroll
        for (int e = 0; e < 4; e++) {
            int idx = tid + e * 256;
            int r = idx >> 4, c = idx & 15;
            int gr = bm + r, gc = k0 + c;
            float v = 0.f;
            if (gr < M && gc < K) v = A[(size_t)gr * K + gc];
            As[c][r] = v;
        }
        #pragma unroll
        for (int e = 0; e < 4; e++) {
            int idx = tid + e * 256;
            int r = idx >> 6, c = idx & 63;
            int gr = k0 + r, gc = bn + c;
            float v = 0.f;
            if (gr < K && gc < N) v = W[(size_t)gr * N + gc];
            Bs[r][c] = v;
        }
        __syncthreads();
        #pragma unroll
        for (int kk = 0; kk < 16; kk++) {
            float4 a4 = *(const float4*)&As[kk][tm];
            float4 b4 = *(const float4*)&Bs[kk][tn];
            float a[4] = {a4.x, a4.y, a4.z, a4.w};
            float b[4] = {b4.x, b4.y, b4.z, b4.w};
            #pragma unroll
            for (int i = 0; i < 4; i++)
                #pragma unroll
                for (int j = 0; j < 4; j++)
                    acc[i][j] = fmaf(a[i], b[j], acc[i][j]);
        }
        __syncthreads();
    }
    #pragma unroll
    for (int i = 0; i < 4; i++) {
        int gm = bm + tm + i;
        if (gm >= M) continue;
        #pragma unroll
        for (int j = 0; j < 4; j++) {
            int gn = bn + tn + j;
            if (gn >= N) continue;
            float v = acc[i][j] + bias[gn];
            if (relu) v = fmaxf(v, 0.f);
            C[(size_t)gm * N + gn] = v;
        }
    }
}

// ================= big GEMM: 128x128 tile, 8x8 micro-tile, f32x2 FMA =================
__global__ __launch_bounds__(256, 2) void gemm128(
    const float* __restrict__ A, const float* __restrict__ B,
    const float* __restrict__ bias, float* __restrict__ C,
    int M, int N, int K)
{
    __shared__ __align__(16) float As[2][16][128];
    __shared__ __align__(16) float Bs[2][16][256];

    int tid = threadIdx.x;
    int bm = blockIdx.y * 128, bn = blockIdx.x * 128;
    int tx = tid & 15, ty = tid >> 4;
    int ar = tid >> 2, ac = (tid & 3) * 4;
    int br = tid >> 5, bc = (tid & 31) * 4;

    bool fullM = (bm + 128 <= M);
    bool fullN = (bn + 128 <= N);
    bool alnA  = ((K & 3) == 0);

    unsigned long long acc[4][8];
    #pragma unroll
    for (int i = 0; i < 4; i++)
        #pragma unroll
        for (int j = 0; j < 8; j++) acc[i][j] = 0ull;

    float a0[4], a1[4], b0[4], b1[4];
    int KT = (K + 15) / 16;

#define LOADTILE(KT_) do {                                                        \
    int k0 = (KT_) * 16;                                                          \
    bool fk = (k0 + 16 <= K);                                                     \
    if (fk && fullM && alnA) {                                                    \
        float4 r0 = *(const float4*)&A[(size_t)(bm + ar) * K + k0 + ac];          \
        float4 r1 = *(const float4*)&A[(size_t)(bm + ar + 64) * K + k0 + ac];     \
        a0[0]=r0.x; a0[1]=r0.y; a0[2]=r0.z; a0[3]=r0.w;                           \
        a1[0]=r1.x; a1[1]=r1.y; a1[2]=r1.z; a1[3]=r1.w;                           \
    } else {                                                                      \
        int gr0 = bm + ar, gr1 = bm + ar + 64;                                    \
        _Pragma("unroll") for (int j = 0; j < 4; j++) {                           \
            int gk = k0 + ac + j;                                                 \
            bool ok = (gk < K);                                                   \
            a0[j] = (ok && gr0 < M) ? A[(size_t)gr0 * K + gk] : 0.f;              \
            a1[j] = (ok && gr1 < M) ? A[(size_t)gr1 * K + gk] : 0.f;              \
        }                                                                         \
    }                                                                             \
    if (fk && fullN) {                                                            \
        float4 r0 = *(const float4*)&B[(size_t)(k0 + br) * N + bn + bc];          \
        float4 r1 = *(const float4*)&B[(size_t)(k0 + br + 8) * N + bn + bc];      \
        b0[0]=r0.x; b0[1]=r0.y; b0[2]=r0.z; b0[3]=r0.w;                           \
        b1[0]=r1.x; b1[1]=r1.y; b1[2]=r1.z; b1[3]=r1.w;                           \
    } else {                                                                      \
        int gk0 = k0 + br, gk1 = k0 + br + 8;                                     \
        _Pragma("unroll") for (int j = 0; j < 4; j++) {                           \
            int gc = bn + bc + j;                                                 \
            bool ok = (gc < N);                                                   \
            b0[j] = (ok && gk0 < K) ? B[(size_t)gk0 * N + gc] : 0.f;              \
            b1[j] = (ok && gk1 < K) ? B[(size_t)gk1 * N + gc] : 0.f;              \
        }                                                                         \
    }                                                                             \
} while (0)

#define STORETILE(BUF_) do {                                                      \
    _Pragma("unroll") for (int j = 0; j < 4; j++) {                               \
        As[BUF_][ac + j][ar]      = a0[j];                                        \
        As[BUF_][ac + j][ar + 64] = a1[j];                                        \
        Bs[BUF_][br][(bc + j) * 2]         = b0[j];                               \
        Bs[BUF_][br][(bc + j) * 2 + 1]     = b0[j];                               \
        Bs[BUF_][br + 8][(bc + j) * 2]     = b1[j];                               \
        Bs[BUF_][br + 8][(bc + j) * 2 + 1] = b1[j];                               \
    }                                                                             \
} while (0)

    LOADTILE(0);
    STORETILE(0);
    __syncthreads();

    for (int kt = 0; kt < KT; kt++) {
        int cur = kt & 1;
        if (kt + 1 < KT) LOADTILE(kt + 1);
        #pragma unroll
        for (int k = 0; k < 16; k++) {
            unsigned long long a2[4], b2[8];
            #pragma unroll
            for (int i = 0; i < 4; i++)
                a2[i] = *(const unsigned long long*)&As[cur][k][ty * 8 + 2 * i];
            #pragma unroll
            for (int j = 0; j < 8; j++)
                b2[j] = *(const unsigned long long*)&Bs[cur][k][(tx + 16 * j) * 2];
            #pragma unroll
            for (int i = 0; i < 4; i++)
                #pragma unroll
                for (int j = 0; j < 8; j++)
                    FMA2(acc[i][j], a2[i], b2[j]);
        }
        if (kt + 1 < KT) STORETILE(cur ^ 1);
        __syncthreads();
    }

    #pragma unroll
    for (int j = 0; j < 8; j++) {
        int col = bn + tx + 16 * j;
        if (col >= N) continue;
        float bb = bias[col];
        #pragma unroll
        for (int i = 0; i < 4; i++) {
            int r0 = bm + ty * 8 + 2 * i;
            float lo = f2lo(acc[i][j]) + bb;
            float hi = f2hi(acc[i][j]) + bb;
            if (r0 < M)     C[(size_t)r0 * N + col] = lo;
            if (r0 + 1 < M) C[(size_t)(r0 + 1) * N + col] = hi;
        }
    }
#undef LOADTILE
#undef STORETILE
}

// ---------------- transpose with output stride: out[c*ostride + r] = in[r*C + c] ----------------
__global__ void transpose_s(const float* __restrict__ in, float* __restrict__ out,
                            int R, int C, int ostride)
{
    __shared__ float tile[32][33];
    int c0 = blockIdx.x * 32, r0 = blockIdx.y * 32;
    for (int j = threadIdx.y; j < 32; j += 8) {
        int r = r0 + j, c = c0 + threadIdx.x;
        tile[j][threadIdx.x] = (r < R && c < C) ? in[(size_t)r * C + c] : 0.f;
    }
    __syncthreads();
    for (int j = threadIdx.y; j < 32; j += 8) {
        int c = c0 + j, r = r0 + threadIdx.x;
        if (c < C && r < R) out[(size_t)c * ostride + r] = tile[threadIdx.x][j];
    }
}

// ---------------- embedding gather ----------------
__global__ void gather_k(const int* __restrict__ caps, const float* __restrict__ emb)
{
    int rid = blockIdx.x;          // 0..799
    int b = rid & 15;
    int nt = rid >> 4;
    int n = nt / Tc, t = nt % Tc;
    int tok = caps[b * (Nc * Tc) + n * Tc + t];
    const float* e = emb + (size_t)tok * Ec;
    float* o = g_x0 + (size_t)rid * Ec;
    for (int i = threadIdx.x; i < Ec; i += blockDim.x) o[i] = e[i];
}

// ---------------- broadcast image h/c into the 4 state slots (k-major, parity 0) ----------------
__global__ void bcast_state_k()
{
    int i = blockIdx.x * blockDim.x + threadIdx.x;   // i = k*16 + b
    if (i < Hc * Bc) {
        int k = i >> 4, b = i & 15;
        float h = g_h0[b * Hc + k];
        float c = g_c0[b * Hc + k];
        #pragma unroll
        for (int s = 0; s < 4; s++) {
            g_hst[s][0][i] = h;
            g_cst[s][i]    = c;
        }
    }
}

// ================= persistent recurrent kernel =================
__device__ __forceinline__ void grid_bar(unsigned& sense)
{
    __syncthreads();
    sense ^= 1;
    if (threadIdx.x == 0) {
        __threadfence();
        unsigned old = atomicAdd(&g_barcnt, 1);
        if (old == NBLK - 1) {
            g_barcnt = 0;
            __threadfence();
            atomicExch(&g_barsense, sense);
        } else {
            while (atomicAdd(&g_barsense, 0) != sense) __nanosleep(64);
        }
        __threadfence();   // fence.gpu -> L1 invalidate, fresh reads after barrier
    }
    __syncthreads();
}

template<int LAYER>
__device__ __forceinline__ void lstm_do_step(
    int tid, int dir, int bkid, int ksub, int bs, int rg,
    float* hs, float* red,
    int n, int tok, int par,
    const float* bias1, const float* xg0d, unsigned& sense)
{
    const int K = LAYER ? (Hc + H2) : Hc;   // 1536 / 512
    int slot = LAYER ? (2 + dir) : dir;
    const float* hglob = &g_hst[slot][par][0];
    float* hout = &g_hst[slot][par ^ 1][0];
    float* cst  = &g_cst[slot][0];
    const float* WT = LAYER ? (g_W1T + (size_t)dir * H4 * (Hc + H2))
                            : (g_W0T + (size_t)dir * H4 * Hc);

    // ---- stage A: stage h (and x1 for layer1) into smem, [k][HSTRIDE] ----
    {
        const float* x1g = g_x1 + (size_t)tok * H2 * Bc;
        int nf4 = K * 4;                  // float4 count = K*16/4
        for (int idx = tid; idx < nf4; idx += 256) {
            int k = idx >> 2, q = idx & 3;
            float4 v;
            if (!LAYER || k < Hc) v = *(const float4*)&hglob[k * Bc + q * 4];
            else                  v = *(const float4*)&x1g[(size_t)(k - Hc) * Bc + q * 4];
            *(float4*)&hs[k * HSTRIDE + q * 4] = v;
        }
    }
    __syncthreads();

    // ---- stage B: partial dots. thread = (rg: 4 rows, bs: 4 b, ksub: K/8 slice) ----
    int r0 = rg * 4;
    const float* Wr[4];
    #pragma unroll
    for (int j = 0; j < 4; j++) {
        int r = r0 + j;
        int m = (r >> 3) * Hc + bkid * 8 + (r & 7);   // gate*512 + ko
        Wr[j] = WT + (size_t)m * K;
    }
    unsigned long long a00 = 0, a01 = 0, a10 = 0, a11 = 0,
                       a20 = 0, a21 = 0, a30 = 0, a31 = 0;
    int K32 = K / 32;
    for (int i = 0; i < K32; i++) {
        int k0 = i * 32 + ksub * 4;
        float4 w0 = *(const float4*)&Wr[0][k0];
        float4 w1 = *(const float4*)&Wr[1][k0];
        float4 w2 = *(const float4*)&Wr[2][k0];
        float4 w3 = *(const float4*)&Wr[3][k0];
        const float* wp0 = (const float*)&w0;
        const float* wp1 = (const float*)&w1;
        const float* wp2 = (const float*)&w2;
        const float* wp3 = (const float*)&w3;
        #pragma unroll
        for (int kk = 0; kk < 4; kk++) {
            ulonglong2 hv = *(const ulonglong2*)&hs[(k0 + kk) * HSTRIDE + bs * 4];
            unsigned long long s0 = splat2(wp0[kk]);
            unsigned long long s1 = splat2(wp1[kk]);
            unsigned long long s2 = splat2(wp2[kk]);
            unsigned long long s3 = splat2(wp3[kk]);
            FMA2(a00, s0, hv.x); FMA2(a01, s0, hv.y);
            FMA2(a10, s1, hv.x); FMA2(a11, s1, hv.y);
            FMA2(a20, s2, hv.x); FMA2(a21, s2, hv.y);
            FMA2(a30, s3, hv.x); FMA2(a31, s3, hv.y);
        }
    }

    // ---- stage C: dump partials ----
    {
        float4 v;
        v = make_float4(f2lo(a00), f2hi(a00), f2lo(a01), f2hi(a01));
        *(float4*)&red[((r0 + 0) * 8 + ksub) * 16 + bs * 4] = v;
        v = make_float4(f2lo(a10), f2hi(a10), f2lo(a11), f2hi(a11));
        *(float4*)&red[((r0 + 1) * 8 + ksub) * 16 + bs * 4] = v;
        v = make_float4(f2lo(a20), f2hi(a20), f2lo(a21), f2hi(a21));
        *(float4*)&red[((r0 + 2) * 8 + ksub) * 16 + bs * 4] = v;
        v = make_float4(f2lo(a30), f2hi(a30), f2lo(a31), f2hi(a31));
        *(float4*)&red[((r0 + 3) * 8 + ksub) * 16 + bs * 4] = v;
    }
    __syncthreads();

    // ---- stage D: reduce + nonlinearity + state update ----
    if (tid < 128) {
        int ko_l = tid & 7, b = tid >> 3;
        int ko = bkid * 8 + ko_l;
        float gsum[4];
        #pragma unroll
        for (int g = 0; g < 4; g++) {
            int r = g * 8 + ko_l;
            float ss = 0.f;
            #pragma unroll
            for (int ks = 0; ks < 8; ks++) ss += red[(r * 8 + ks) * 16 + b];
            gsum[g] = ss;
        }
        float pi, pf, pg, po;
        if (LAYER) {
            pi = bias1[ko]; pf = bias1[512 + ko];
            pg = bias1[1024 + ko]; po = bias1[1536 + ko];
        } else {
            const float* xg = xg0d + ((size_t)(n * Tc + tok) * Bc + b) * H4 + ko;
            pi = xg[0]; pf = xg[512]; pg = xg[1024]; po = xg[1536];
        }
        float gi = gsum[0] + pi, gf = gsum[1] + pf, gg = gsum[2] + pg, go = gsum[3] + po;
        float si = 1.f / (1.f + expf(-gi));
        float sf = 1.f / (1.f + expf(-gf));
        float so = 1.f / (1.f + expf(-go));
        int idx = ko * Bc + b;
        float cn = sf * cst[idx] + si * tanhf(gg);
        float hn = so * tanhf(cn);
        cst[idx]  = cn;
        hout[idx] = hn;
        if (LAYER) {
            g_out1[((size_t)(n * Tc + tok) * Bc + b) * H2 + dir * Hc + ko] = hn;
        } else {
            g_x1[((size_t)tok * H2 + dir * Hc + ko) * Bc + b] = hn;
        }
    }
    grid_bar(sense);
}

__global__ __launch_bounds__(256, 1) void lstm_persist(
    const float* __restrict__ b1f_, const float* __restrict__ b1b_)
{
    extern __shared__ float smem[];
    float* hs  = smem;                         // [1536][HSTRIDE]
    float* red = smem + 1536 * HSTRIDE;        // [32][8][16]

    int tid = threadIdx.x, bid = blockIdx.x;
    int dir = bid >> 6, bkid = bid & 63;
    int ksub = tid & 7, bs = (tid >> 3) & 3, rg = tid >> 5;

    const float* bias1 = dir ? b1b_ : b1f_;
    const float* xg0d  = g_xg0 + (size_t)dir * NTB * H4;

    unsigned sense = 0;
    int p0 = 0, p1 = 0;

    for (int t = 0; t < Tc; t++) {
        for (int n = 0; n < Nc; n++) {
            int L = t + 1;
            for (int s = 0; s < L; s++) {
                int tok = dir ? (L - 1 - s) : s;
                lstm_do_step<0>(tid, dir, bkid, ksub, bs, rg, hs, red,
                                n, tok, p0, bias1, xg0d, sense);
                p0 ^= 1;
            }
            for (int s = 0; s < L; s++) {
                int tok = dir ? (L - 1 - s) : s;
                lstm_do_step<1>(tid, dir, bkid, ksub, bs, rg, hs, red,
                                n, tok, p1, bias1, xg0d, sense);
                p1 ^= 1;
            }
        }
    }
}

// ---------------- host ----------------
extern "C" void kernel_launch(void* const* d_in, const int* in_sizes, int n_in,
                              void* d_out, int out_size)
{
    const float* img   = (const float*)d_in[0];
    const int*   caps  = (const int*)  d_in[1];
    const float* Wh1   = (const float*)d_in[2];
    const float* bh1   = (const float*)d_in[3];
    const float* Wh2   = (const float*)d_in[4];
    const float* bh2   = (const float*)d_in[5];
    const float* Wc1   = (const float*)d_in[6];
    const float* bc1   = (const float*)d_in[7];
    const float* Wc2   = (const float*)d_in[8];
    const float* bc2   = (const float*)d_in[9];
    const float* emb   = (const float*)d_in[10];
    const float* Wih0f = (const float*)d_in[11];
    const float* Whh0f = (const float*)d_in[12];
    const float* b0f   = (const float*)d_in[13];
    const float* Wih0b = (const float*)d_in[14];
    const float* Whh0b = (const float*)d_in[15];
    const float* b0b   = (const float*)d_in[16];
    const float* Wih1f = (const float*)d_in[17];
    const float* Whh1f = (const float*)d_in[18];
    const float* b1f   = (const float*)d_in[19];
    const float* Wih1b = (const float*)d_in[20];
    const float* Whh1b = (const float*)d_in[21];
    const float* b1b   = (const float*)d_in[22];
    const float* Wfc   = (const float*)d_in[23];
    const float* bfc   = (const float*)d_in[24];
    float* outp = (float*)d_out;

    float *p_tmp, *p_h0, *p_c0, *p_x0, *p_xg0, *p_out1, *p_W0T, *p_W1T;
    cudaGetSymbolAddress((void**)&p_tmp,  g_tmp);
    cudaGetSymbolAddress((void**)&p_h0,   g_h0);
    cudaGetSymbolAddress((void**)&p_c0,   g_c0);
    cudaGetSymbolAddress((void**)&p_x0,   g_x0);
    cudaGetSymbolAddress((void**)&p_xg0,  g_xg0);
    cudaGetSymbolAddress((void**)&p_out1, g_out1);
    cudaGetSymbolAddress((void**)&p_W0T,  g_W0T);
    cudaGetSymbolAddress((void**)&p_W1T,  g_W1T);

    const size_t W1ROW = (size_t)H4 * (Hc + H2);

    dim3 tb(32, 8);
    // W0T: [2048][512] per dir
    transpose_s<<<dim3(H4/32, Hc/32), tb>>>(Whh0f, p_W0T,               Hc, H4, Hc);
    transpose_s<<<dim3(H4/32, Hc/32), tb>>>(Whh0b, p_W0T + (size_t)H4*Hc, Hc, H4, Hc);
    // W1T fused: [2048][1536] per dir: cols 0..511 = WhhT, 512..1535 = WihT
    transpose_s<<<dim3(H4/32, Hc/32), tb>>>(Whh1f, p_W1T,               Hc, H4, Hc + H2);
    transpose_s<<<dim3(H4/32, H2/32), tb>>>(Wih1f, p_W1T + Hc,          H2, H4, Hc + H2);
    transpose_s<<<dim3(H4/32, Hc/32), tb>>>(Whh1b, p_W1T + W1ROW,       Hc, H4, Hc + H2);
    transpose_s<<<dim3(H4/32, H2/32), tb>>>(Wih1b, p_W1T + W1ROW + Hc,  H2, H4, Hc + H2);

    // image MLPs -> g_h0 / g_c0 ([b][k]), then broadcast into k-major state slots
    sgemm_kernel<<<dim3(H2/64, 1), 256>>>(img,   Wh1, bh1, p_tmp, Bc, H2, Fc, 1);
    sgemm_kernel<<<dim3(Hc/64, 1), 256>>>(p_tmp, Wh2, bh2, p_h0,  Bc, Hc, H2, 1);
    sgemm_kernel<<<dim3(H2/64, 1), 256>>>(img,   Wc1, bc1, p_tmp, Bc, H2, Fc, 1);
    sgemm_kernel<<<dim3(Hc/64, 1), 256>>>(p_tmp, Wc2, bc2, p_c0,  Bc, Hc, H2, 1);
    bcast_state_k<<<(Hc*Bc + 255)/256, 256>>>();

    // embeddings + layer0 input gates (shared by all 50 bilstm calls)
    gather_k<<<NTB, 256>>>(caps, emb);
    gemm128<<<dim3((H4+127)/128, (NTB+127)/128), 256>>>(p_x0, Wih0f, b0f, p_xg0,                    NTB, H4, Ec);
    gemm128<<<dim3((H4+127)/128, (NTB+127)/128), 256>>>(p_x0, Wih0b, b0b, p_xg0 + (size_t)NTB * H4, NTB, H4, Ec);

    // persistent recurrent chain (all 550 steps, internal grid barriers)
    const int SMEM_BYTES = (1536 * HSTRIDE + 32 * 8 * 16) * 4;   // 139264
    cudaFuncSetAttribute(lstm_persist, cudaFuncAttributeMaxDynamicSharedMemorySize, SMEM_BYTES);
    lstm_persist<<<NBLK, 256, SMEM_BYTES>>>(b1f, b1b);

    // final FC: out[800, 30000] = g_out1 @ Wfc + bfc
    gemm128<<<dim3((Vc + 127)/128, (NTB + 127)/128), 256>>>(p_out1, Wfc, bfc, outp, NTB, Vc, H2);
}

// round 7
// speedup vs baseline: 1.8116x; 1.0476x over previous
#include <cuda_runtime.h>
#include <cuda_bf16.h>
#include <math.h>
#include <stdint.h>

// Problem constants
#define Bc 16
#define Nc 5
#define Tc 10
#define Hc 512
#define Ec 250
#define Vc 30000
#define Fc 2048
#define H4 2048
#define H2 1024
#define NTB (Nc*Tc*Bc)   // 800
#define NBLK 128
#define HSTRIDE 20

// packed fp32x2 FMA (SASS FFMA2)
#define FMA2(d, a, b) asm("fma.rn.f32x2 %0, %1, %2, %0;" : "+l"(d) : "l"(a), "l"(b))

__device__ __forceinline__ float f2lo(unsigned long long v) { return __uint_as_float((unsigned)v); }
__device__ __forceinline__ float f2hi(unsigned long long v) { return __uint_as_float((unsigned)(v >> 32)); }
__device__ __forceinline__ unsigned long long splat2(float w) {
    unsigned long long d;
    asm("mov.b64 %0, {%1, %1};" : "=l"(d) : "r"(__float_as_uint(w)));
    return d;
}

// ---------------- device scratch ----------------
__device__ __align__(16) float g_tmp[Bc*H2];
__device__ __align__(16) float g_h0[Bc*Hc];
__device__ __align__(16) float g_c0[Bc*Hc];
__device__ __align__(16) float g_hst[4][2][Hc*Bc];
__device__ __align__(16) float g_cst[4][Hc*Bc];
__device__ __align__(16) float g_x0[NTB*Ec];
__device__ __align__(16) float g_xg0[2*NTB*H4];
__device__ __align__(16) float g_x1[Tc*H2*Bc];
__device__ __align__(16) float g_out1[NTB*H2];
__device__ __align__(16) float g_W0T[2*H4*Hc];
__device__ __align__(16) float g_W1T[2*H4*(Hc+H2)];
__device__ __align__(16) __nv_bfloat16 g_Ahi[NTB*H2];
__device__ __align__(16) __nv_bfloat16 g_Alo[NTB*H2];
__device__ __align__(16) __nv_bfloat16 g_Bhi[(size_t)Vc*H2];
__device__ __align__(16) __nv_bfloat16 g_Blo[(size_t)Vc*H2];

__device__ unsigned g_barcnt = 0;
__device__ unsigned g_barsense = 0;

// ================= small fp32 GEMM (tiny image MLPs) =================
__global__ __launch_bounds__(256) void sgemm_kernel(
    const float* __restrict__ A, const float* __restrict__ W,
    const float* __restrict__ bias, float* __restrict__ C,
    int M, int N, int K, int relu)
{
    __shared__ float As[16][64];
    __shared__ float Bs[16][64];
    int bm = blockIdx.y * 64, bn = blockIdx.x * 64;
    int tid = threadIdx.x;
    int tm = (tid >> 4) << 2;
    int tn = (tid & 15) << 2;
    float acc[4][4] = {};
    for (int k0 = 0; k0 < K; k0 += 16) {
        #pragma unroll
        for (int e = 0; e < 4; e++) {
            int idx = tid + e * 256;
            int r = idx >> 4, c = idx & 15;
            int gr = bm + r, gc = k0 + c;
            float v = 0.f;
            if (gr < M && gc < K) v = A[(size_t)gr * K + gc];
            As[c][r] = v;
        }
        #pragma unroll
        for (int e = 0; e < 4; e++) {
            int idx = tid + e * 256;
            int r = idx >> 6, c = idx & 63;
            int gr = k0 + r, gc = bn + c;
            float v = 0.f;
            if (gr < K && gc < N) v = W[(size_t)gr * N + gc];
            Bs[r][c] = v;
        }
        __syncthreads();
        #pragma unroll
        for (int kk = 0; kk < 16; kk++) {
            float4 a4 = *(const float4*)&As[kk][tm];
            float4 b4 = *(const float4*)&Bs[kk][tn];
            float a[4] = {a4.x, a4.y, a4.z, a4.w};
            float b[4] = {b4.x, b4.y, b4.z, b4.w};
            #pragma unroll
            for (int i = 0; i < 4; i++)
                #pragma unroll
                for (int j = 0; j < 4; j++)
                    acc[i][j] = fmaf(a[i], b[j], acc[i][j]);
        }
        __syncthreads();
    }
    #pragma unroll
    for (int i = 0; i < 4; i++) {
        int gm = bm + tm + i;
        if (gm >= M) continue;
        #pragma unroll
        for (int j = 0; j < 4; j++) {
            int gn = bn + tn + j;
            if (gn >= N) continue;
            float v = acc[i][j] + bias[gn];
            if (relu) v = fmaxf(v, 0.f);
            C[(size_t)gm * N + gn] = v;
        }
    }
}

// ================= fp32 GEMM 128x128 (xg0 only) =================
__global__ __launch_bounds__(256, 2) void gemm128(
    const float* __restrict__ A, const float* __restrict__ B,
    const float* __restrict__ bias, float* __restrict__ C,
    int M, int N, int K)
{
    __shared__ __align__(16) float As[2][16][128];
    __shared__ __align__(16) float Bs[2][16][256];

    int tid = threadIdx.x;
    int bm = blockIdx.y * 128, bn = blockIdx.x * 128;
    int tx = tid & 15, ty = tid >> 4;
    int ar = tid >> 2, ac = (tid & 3) * 4;
    int br = tid >> 5, bc = (tid & 31) * 4;

    bool fullM = (bm + 128 <= M);
    bool fullN = (bn + 128 <= N);
    bool alnA  = ((K & 3) == 0);

    unsigned long long acc[4][8];
    #pragma unroll
    for (int i = 0; i < 4; i++)
        #pragma unroll
        for (int j = 0; j < 8; j++) acc[i][j] = 0ull;

    float a0[4], a1[4], b0[4], b1[4];
    int KT = (K + 15) / 16;

#define LOADTILE(KT_) do {                                                        \
    int k0 = (KT_) * 16;                                                          \
    bool fk = (k0 + 16 <= K);                                                     \
    if (fk && fullM && alnA) {                                                    \
        float4 r0 = *(const float4*)&A[(size_t)(bm + ar) * K + k0 + ac];          \
        float4 r1 = *(const float4*)&A[(size_t)(bm + ar + 64) * K + k0 + ac];     \
        a0[0]=r0.x; a0[1]=r0.y; a0[2]=r0.z; a0[3]=r0.w;                           \
        a1[0]=r1.x; a1[1]=r1.y; a1[2]=r1.z; a1[3]=r1.w;                           \
    } else {                                                                      \
        int gr0 = bm + ar, gr1 = bm + ar + 64;                                    \
        _Pragma("unroll") for (int j = 0; j < 4; j++) {                           \
            int gk = k0 + ac + j;                                                 \
            bool ok = (gk < K);                                                   \
            a0[j] = (ok && gr0 < M) ? A[(size_t)gr0 * K + gk] : 0.f;              \
            a1[j] = (ok && gr1 < M) ? A[(size_t)gr1 * K + gk] : 0.f;              \
        }                                                                         \
    }                                                                             \
    if (fk && fullN) {                                                            \
        float4 r0 = *(const float4*)&B[(size_t)(k0 + br) * N + bn + bc];          \
        float4 r1 = *(const float4*)&B[(size_t)(k0 + br + 8) * N + bn + bc];      \
        b0[0]=r0.x; b0[1]=r0.y; b0[2]=r0.z; b0[3]=r0.w;                           \
        b1[0]=r1.x; b1[1]=r1.y; b1[2]=r1.z; b1[3]=r1.w;                           \
    } else {                                                                      \
        int gk0 = k0 + br, gk1 = k0 + br + 8;                                     \
        _Pragma("unroll") for (int j = 0; j < 4; j++) {                           \
            int gc = bn + bc + j;                                                 \
            bool ok = (gc < N);                                                   \
            b0[j] = (ok && gk0 < K) ? B[(size_t)gk0 * N + gc] : 0.f;              \
            b1[j] = (ok && gk1 < K) ? B[(size_t)gk1 * N + gc] : 0.f;              \
        }                                                                         \
    }                                                                             \
} while (0)

#define STORETILE(BUF_) do {                                                      \
    _Pragma("unroll") for (int j = 0; j < 4; j++) {                               \
        As[BUF_][ac + j][ar]      = a0[j];                                        \
        As[BUF_][ac + j][ar + 64] = a1[j];                                        \
        Bs[BUF_][br][(bc + j) * 2]         = b0[j];                               \
        Bs[BUF_][br][(bc + j) * 2 + 1]     = b0[j];                               \
        Bs[BUF_][br + 8][(bc + j) * 2]     = b1[j];                               \
        Bs[BUF_][br + 8][(bc + j) * 2 + 1] = b1[j];                               \
    }                                                                             \
} while (0)

    LOADTILE(0);
    STORETILE(0);
    __syncthreads();

    for (int kt = 0; kt < KT; kt++) {
        int cur = kt & 1;
        if (kt + 1 < KT) LOADTILE(kt + 1);
        #pragma unroll
        for (int k = 0; k < 16; k++) {
            unsigned long long a2[4], b2[8];
            #pragma unroll
            for (int i = 0; i < 4; i++)
                a2[i] = *(const unsigned long long*)&As[cur][k][ty * 8 + 2 * i];
            #pragma unroll
            for (int j = 0; j < 8; j++)
                b2[j] = *(const unsigned long long*)&Bs[cur][k][(tx + 16 * j) * 2];
            #pragma unroll
            for (int i = 0; i < 4; i++)
                #pragma unroll
                for (int j = 0; j < 8; j++)
                    FMA2(acc[i][j], a2[i], b2[j]);
        }
        if (kt + 1 < KT) STORETILE(cur ^ 1);
        __syncthreads();
    }

    #pragma unroll
    for (int j = 0; j < 8; j++) {
        int col = bn + tx + 16 * j;
        if (col >= N) continue;
        float bb = bias[col];
        #pragma unroll
        for (int i = 0; i < 4; i++) {
            int r0 = bm + ty * 8 + 2 * i;
            float lo = f2lo(acc[i][j]) + bb;
            float hi = f2hi(acc[i][j]) + bb;
            if (r0 < M)     C[(size_t)r0 * N + col] = lo;
            if (r0 + 1 < M) C[(size_t)(r0 + 1) * N + col] = hi;
        }
    }
#undef LOADTILE
#undef STORETILE
}

// ================= bf16-split mma.sync FC: out[800,30000] = out1 @ Wfc + bfc =================
#define FCBM 128
#define FCBN 128
#define FCBK 64
#define PADK 72                      // bf16 k-stride in smem (36 words -> conflict-free)
#define FC_SMEM (4 * FCBM * PADK * 2)   // Ah, Al, Bh, Bl : 73728 bytes

__device__ __forceinline__ void mma16816(
    float& c0, float& c1, float& c2, float& c3,
    uint32_t a0, uint32_t a1, uint32_t a2, uint32_t a3,
    uint32_t b0, uint32_t b1)
{
    asm volatile(
        "mma.sync.aligned.m16n8k16.row.col.f32.bf16.bf16.f32 "
        "{%0,%1,%2,%3}, {%4,%5,%6,%7}, {%8,%9}, {%0,%1,%2,%3};"
        : "+f"(c0), "+f"(c1), "+f"(c2), "+f"(c3)
        : "r"(a0), "r"(a1), "r"(a2), "r"(a3), "r"(b0), "r"(b1));
}

__global__ __launch_bounds__(256) void fc_wmma(
    const float* __restrict__ bias, float* __restrict__ out)
{
    extern __shared__ __align__(16) __nv_bfloat16 sm[];
    __nv_bfloat16* sAh = sm;
    __nv_bfloat16* sAl = sm + FCBM * PADK;
    __nv_bfloat16* sBh = sm + 2 * FCBM * PADK;
    __nv_bfloat16* sBl = sm + 3 * FCBM * PADK;

    int tid = threadIdx.x;
    int wid = tid >> 5, lane = tid & 31;
    int g = lane >> 2, q = lane & 3;
    int wm = wid & 3, wn = wid >> 2;     // warp tile: rows wm*32..+31, cols wn*64..+63
    int bm = blockIdx.y * FCBM, bn = blockIdx.x * FCBN;

    const uint4* A4h = (const uint4*)g_Ahi;
    const uint4* A4l = (const uint4*)g_Alo;
    const uint4* B4h = (const uint4*)g_Bhi;
    const uint4* B4l = (const uint4*)g_Blo;
    const uint4 z4 = make_uint4(0, 0, 0, 0);

    float acc[2][8][4];
    #pragma unroll
    for (int i = 0; i < 2; i++)
        #pragma unroll
        for (int j = 0; j < 8; j++)
            #pragma unroll
            for (int e = 0; e < 4; e++) acc[i][j][e] = 0.f;

    const uint32_t* sA32h = (const uint32_t*)sAh;
    const uint32_t* sA32l = (const uint32_t*)sAl;
    const uint32_t* sB32h = (const uint32_t*)sBh;
    const uint32_t* sB32l = (const uint32_t*)sBl;

    for (int kc = 0; kc < H2 / FCBK; kc++) {        // 16 chunks
        __syncthreads();
        // stage A [128 m][64 k] hi+lo
        #pragma unroll
        for (int it = 0; it < 4; it++) {
            int idx = tid + it * 256;               // 0..1023
            int m = idx >> 3, kg = idx & 7;
            int gm = bm + m;
            size_t gi = (size_t)gm * (H2 / 8) + kc * 8 + kg;
            uint4 vh = z4, vl = z4;
            if (gm < NTB) { vh = A4h[gi]; vl = A4l[gi]; }
            *(uint4*)&sAh[m * PADK + kg * 8] = vh;
            *(uint4*)&sAl[m * PADK + kg * 8] = vl;
        }
        // stage B [128 n][64 k] hi+lo
        #pragma unroll
        for (int it = 0; it < 4; it++) {
            int idx = tid + it * 256;
            int n = idx >> 3, kg = idx & 7;
            int gn = bn + n;
            uint4 vh = z4, vl = z4;
            if (gn < Vc) {
                size_t gi = (size_t)gn * (H2 / 8) + kc * 8 + kg;
                vh = B4h[gi]; vl = B4l[gi];
            }
            *(uint4*)&sBh[n * PADK + kg * 8] = vh;
            *(uint4*)&sBl[n * PADK + kg * 8] = vl;
        }
        __syncthreads();

        #pragma unroll
        for (int ks = 0; ks < 4; ks++) {            // k16 within chunk
            uint32_t ah[2][4], al[2][4];
            #pragma unroll
            for (int mi = 0; mi < 2; mi++) {
                int r0 = (wm * 32 + mi * 16 + g) * (PADK / 2);
                int r8 = r0 + 8 * (PADK / 2);
                int w0 = ks * 8 + q, w4 = w0 + 4;
                ah[mi][0] = sA32h[r0 + w0]; ah[mi][1] = sA32h[r8 + w0];
                ah[mi][2] = sA32h[r0 + w4]; ah[mi][3] = sA32h[r8 + w4];
                al[mi][0] = sA32l[r0 + w0]; al[mi][1] = sA32l[r8 + w0];
                al[mi][2] = sA32l[r0 + w4]; al[mi][3] = sA32l[r8 + w4];
            }
            #pragma unroll
            for (int ni = 0; ni < 8; ni++) {
                int nr = (wn * 64 + ni * 8 + g) * (PADK / 2);
                int w0 = ks * 8 + q, w4 = w0 + 4;
                uint32_t bh0 = sB32h[nr + w0], bh1 = sB32h[nr + w4];
                uint32_t bl0 = sB32l[nr + w0], bl1 = sB32l[nr + w4];
                #pragma unroll
                for (int mi = 0; mi < 2; mi++) {
                    float* c = acc[mi][ni];
                    mma16816(c[0], c[1], c[2], c[3],
                             ah[mi][0], ah[mi][1], ah[mi][2], ah[mi][3], bh0, bh1);
                    mma16816(c[0], c[1], c[2], c[3],
                             al[mi][0], al[mi][1], al[mi][2], al[mi][3], bh0, bh1);
                    mma16816(c[0], c[1], c[2], c[3],
                             ah[mi][0], ah[mi][1], ah[mi][2], ah[mi][3], bl0, bl1);
                }
            }
        }
    }

    // epilogue: direct stores (c0,c1 adjacent cols; c2,c3 at row+8)
    #pragma unroll
    for (int mi = 0; mi < 2; mi++) {
        int row0 = bm + wm * 32 + mi * 16 + g;
        int row1 = row0 + 8;
        #pragma unroll
        for (int ni = 0; ni < 8; ni++) {
            int col = bn + wn * 64 + ni * 8 + q * 2;
            if (col >= Vc) continue;
            float b0 = bias[col], b1 = bias[col + 1];
            const float* c = acc[mi][ni];
            if (row0 < NTB) {
                float2 v = make_float2(c[0] + b0, c[1] + b1);
                *(float2*)&out[(size_t)row0 * Vc + col] = v;
            }
            if (row1 < NTB) {
                float2 v = make_float2(c[2] + b0, c[3] + b1);
                *(float2*)&out[(size_t)row1 * Vc + col] = v;
            }
        }
    }
}

// ---------------- bf16 split conversions ----------------
__global__ void convA_k(const float* __restrict__ in)
{
    int i = blockIdx.x * 256 + threadIdx.x;
    if (i < NTB * H2) {
        float v = in[i];
        __nv_bfloat16 h = __float2bfloat16(v);
        g_Ahi[i] = h;
        g_Alo[i] = __float2bfloat16(v - __bfloat162float(h));
    }
}

// Wfc[1024][30000] -> Bhi/Blo[30000][1024] (transposed, split)
__global__ void convB_k(const float* __restrict__ W)
{
    __shared__ float t[32][33];
    int n0 = blockIdx.x * 32, k0 = blockIdx.y * 32;
    for (int j = threadIdx.y; j < 32; j += 8) {
        int k = k0 + j, n = n0 + threadIdx.x;
        t[j][threadIdx.x] = (n < Vc) ? W[(size_t)k * Vc + n] : 0.f;
    }
    __syncthreads();
    for (int j = threadIdx.y; j < 32; j += 8) {
        int n = n0 + j, k = k0 + threadIdx.x;
        if (n < Vc) {
            float v = t[threadIdx.x][j];
            __nv_bfloat16 h = __float2bfloat16(v);
            g_Bhi[(size_t)n * H2 + k] = h;
            g_Blo[(size_t)n * H2 + k] = __float2bfloat16(v - __bfloat162float(h));
        }
    }
}

// ---------------- transpose with output stride ----------------
__global__ void transpose_s(const float* __restrict__ in, float* __restrict__ out,
                            int R, int C, int ostride)
{
    __shared__ float tile[32][33];
    int c0 = blockIdx.x * 32, r0 = blockIdx.y * 32;
    for (int j = threadIdx.y; j < 32; j += 8) {
        int r = r0 + j, c = c0 + threadIdx.x;
        tile[j][threadIdx.x] = (r < R && c < C) ? in[(size_t)r * C + c] : 0.f;
    }
    __syncthreads();
    for (int j = threadIdx.y; j < 32; j += 8) {
        int c = c0 + j, r = r0 + threadIdx.x;
        if (c < C && r < R) out[(size_t)c * ostride + r] = tile[threadIdx.x][j];
    }
}

// ---------------- embedding gather ----------------
__global__ void gather_k(const int* __restrict__ caps, const float* __restrict__ emb)
{
    int rid = blockIdx.x;
    int b = rid & 15;
    int nt = rid >> 4;
    int n = nt / Tc, t = nt % Tc;
    int tok = caps[b * (Nc * Tc) + n * Tc + t];
    const float* e = emb + (size_t)tok * Ec;
    float* o = g_x0 + (size_t)rid * Ec;
    for (int i = threadIdx.x; i < Ec; i += blockDim.x) o[i] = e[i];
}

// ---------------- broadcast image h/c ----------------
__global__ void bcast_state_k()
{
    int i = blockIdx.x * blockDim.x + threadIdx.x;
    if (i < Hc * Bc) {
        int k = i >> 4, b = i & 15;
        float h = g_h0[b * Hc + k];
        float c = g_c0[b * Hc + k];
        #pragma unroll
        for (int s = 0; s < 4; s++) {
            g_hst[s][0][i] = h;
            g_cst[s][i]    = c;
        }
    }
}

// ================= persistent recurrent kernel =================
__device__ __forceinline__ void grid_bar(unsigned& sense)
{
    __syncthreads();
    sense ^= 1;
    if (threadIdx.x == 0) {
        __threadfence();
        unsigned old = atomicAdd(&g_barcnt, 1);
        if (old == NBLK - 1) {
            g_barcnt = 0;
            __threadfence();
            atomicExch(&g_barsense, sense);
        } else {
            while (atomicAdd(&g_barsense, 0) != sense) __nanosleep(64);
        }
        __threadfence();
    }
    __syncthreads();
}

template<int LAYER>
__device__ __forceinline__ void lstm_do_step(
    int tid, int dir, int bkid, int ksub, int bs, int rg,
    float* hs, float* red,
    int n, int tok, int par,
    const float* bias1, const float* xg0d, unsigned& sense)
{
    const int K = LAYER ? (Hc + H2) : Hc;
    int slot = LAYER ? (2 + dir) : dir;
    const float* hglob = &g_hst[slot][par][0];
    float* hout = &g_hst[slot][par ^ 1][0];
    float* cst  = &g_cst[slot][0];
    const float* WT = LAYER ? (g_W1T + (size_t)dir * H4 * (Hc + H2))
                            : (g_W0T + (size_t)dir * H4 * Hc);

    // stage A: stage h (and x1 for layer1) into smem
    {
        const float* x1g = g_x1 + (size_t)tok * H2 * Bc;
        int nf4 = K * 4;
        for (int idx = tid; idx < nf4; idx += 256) {
            int k = idx >> 2, q = idx & 3;
            float4 v;
            if (!LAYER || k < Hc) v = *(const float4*)&hglob[k * Bc + q * 4];
            else                  v = *(const float4*)&x1g[(size_t)(k - Hc) * Bc + q * 4];
            *(float4*)&hs[k * HSTRIDE + q * 4] = v;
        }
    }
    __syncthreads();

    // stage B: partial dots with register-double-buffered weight loads
    int r0 = rg * 4;
    const float4* p0;
    const float4* p1;
    const float4* p2;
    const float4* p3;
    {
        int m0 = ((r0 + 0) >> 3) * Hc + bkid * 8 + ((r0 + 0) & 7);
        int m1 = ((r0 + 1) >> 3) * Hc + bkid * 8 + ((r0 + 1) & 7);
        int m2 = ((r0 + 2) >> 3) * Hc + bkid * 8 + ((r0 + 2) & 7);
        int m3 = ((r0 + 3) >> 3) * Hc + bkid * 8 + ((r0 + 3) & 7);
        p0 = (const float4*)(WT + (size_t)m0 * K);
        p1 = (const float4*)(WT + (size_t)m1 * K);
        p2 = (const float4*)(WT + (size_t)m2 * K);
        p3 = (const float4*)(WT + (size_t)m3 * K);
    }
    unsigned long long a00 = 0, a01 = 0, a10 = 0, a11 = 0,
                       a20 = 0, a21 = 0, a30 = 0, a31 = 0;
    const int K32 = K / 32;
    float4 c0 = p0[ksub], c1 = p1[ksub], c2 = p2[ksub], c3 = p3[ksub];
    #pragma unroll 2
    for (int i = 0; i < K32; i++) {
        int nf = ((i + 1 < K32) ? (i + 1) : i) * 8 + ksub;
        float4 n0 = p0[nf], n1 = p1[nf], n2 = p2[nf], n3 = p3[nf];
        int k0 = i * 32 + ksub * 4;
        const float* wp0 = (const float*)&c0;
        const float* wp1 = (const float*)&c1;
        const float* wp2 = (const float*)&c2;
        const float* wp3 = (const float*)&c3;
        #pragma unroll
        for (int kk = 0; kk < 4; kk++) {
            ulonglong2 hv = *(const ulonglong2*)&hs[(k0 + kk) * HSTRIDE + bs * 4];
            unsigned long long s0 = splat2(wp0[kk]);
            unsigned long long s1 = splat2(wp1[kk]);
            unsigned long long s2 = splat2(wp2[kk]);
            unsigned long long s3 = splat2(wp3[kk]);
            FMA2(a00, s0, hv.x); FMA2(a01, s0, hv.y);
            FMA2(a10, s1, hv.x); FMA2(a11, s1, hv.y);
            FMA2(a20, s2, hv.x); FMA2(a21, s2, hv.y);
            FMA2(a30, s3, hv.x); FMA2(a31, s3, hv.y);
        }
        c0 = n0; c1 = n1; c2 = n2; c3 = n3;
    }

    // stage C: dump partials
    {
        float4 v;
        v = make_float4(f2lo(a00), f2hi(a00), f2lo(a01), f2hi(a01));
        *(float4*)&red[((r0 + 0) * 8 + ksub) * 16 + bs * 4] = v;
        v = make_float4(f2lo(a10), f2hi(a10), f2lo(a11), f2hi(a11));
        *(float4*)&red[((r0 + 1) * 8 + ksub) * 16 + bs * 4] = v;
        v = make_float4(f2lo(a20), f2hi(a20), f2lo(a21), f2hi(a21));
        *(float4*)&red[((r0 + 2) * 8 + ksub) * 16 + bs * 4] = v;
        v = make_float4(f2lo(a30), f2hi(a30), f2lo(a31), f2hi(a31));
        *(float4*)&red[((r0 + 3) * 8 + ksub) * 16 + bs * 4] = v;
    }
    __syncthreads();

    // stage D: reduce + nonlinearity + state update
    if (tid < 128) {
        int ko_l = tid & 7, b = tid >> 3;
        int ko = bkid * 8 + ko_l;
        float gsum[4];
        #pragma unroll
        for (int g = 0; g < 4; g++) {
            int r = g * 8 + ko_l;
            float ss = 0.f;
            #pragma unroll
            for (int ks = 0; ks < 8; ks++) ss += red[(r * 8 + ks) * 16 + b];
            gsum[g] = ss;
        }
        float pi, pf, pg, po;
        if (LAYER) {
            pi = bias1[ko]; pf = bias1[512 + ko];
            pg = bias1[1024 + ko]; po = bias1[1536 + ko];
        } else {
            const float* xg = xg0d + ((size_t)(n * Tc + tok) * Bc + b) * H4 + ko;
            pi = xg[0]; pf = xg[512]; pg = xg[1024]; po = xg[1536];
        }
        float gi = gsum[0] + pi, gf = gsum[1] + pf, gg = gsum[2] + pg, go = gsum[3] + po;
        float si = 1.f / (1.f + expf(-gi));
        float sf = 1.f / (1.f + expf(-gf));
        float so = 1.f / (1.f + expf(-go));
        int idx = ko * Bc + b;
        float cn = sf * cst[idx] + si * tanhf(gg);
        float hn = so * tanhf(cn);
        cst[idx]  = cn;
        hout[idx] = hn;
        if (LAYER) {
            g_out1[((size_t)(n * Tc + tok) * Bc + b) * H2 + dir * Hc + ko] = hn;
        } else {
            g_x1[((size_t)tok * H2 + dir * Hc + ko) * Bc + b] = hn;
        }
    }
    grid_bar(sense);
}

__global__ __launch_bounds__(256, 1) void lstm_persist(
    const float* __restrict__ b1f_, const float* __restrict__ b1b_)
{
    extern __shared__ float smemf[];
    float* hs  = smemf;
    float* red = smemf + 1536 * HSTRIDE;

    int tid = threadIdx.x, bid = blockIdx.x;
    int dir = bid >> 6, bkid = bid & 63;
    int ksub = tid & 7, bs = (tid >> 3) & 3, rg = tid >> 5;

    const float* bias1 = dir ? b1b_ : b1f_;
    const float* xg0d  = g_xg0 + (size_t)dir * NTB * H4;

    unsigned sense = 0;
    int p0 = 0, p1 = 0;

    for (int t = 0; t < Tc; t++) {
        for (int n = 0; n < Nc; n++) {
            int L = t + 1;
            for (int s = 0; s < L; s++) {
                int tok = dir ? (L - 1 - s) : s;
                lstm_do_step<0>(tid, dir, bkid, ksub, bs, rg, hs, red,
                                n, tok, p0, bias1, xg0d, sense);
                p0 ^= 1;
            }
            for (int s = 0; s < L; s++) {
                int tok = dir ? (L - 1 - s) : s;
                lstm_do_step<1>(tid, dir, bkid, ksub, bs, rg, hs, red,
                                n, tok, p1, bias1, xg0d, sense);
                p1 ^= 1;
            }
        }
    }
}

// ---------------- host ----------------
extern "C" void kernel_launch(void* const* d_in, const int* in_sizes, int n_in,
                              void* d_out, int out_size)
{
    const float* img   = (const float*)d_in[0];
    const int*   caps  = (const int*)  d_in[1];
    const float* Wh1   = (const float*)d_in[2];
    const float* bh1   = (const float*)d_in[3];
    const float* Wh2   = (const float*)d_in[4];
    const float* bh2   = (const float*)d_in[5];
    const float* Wc1   = (const float*)d_in[6];
    const float* bc1   = (const float*)d_in[7];
    const float* Wc2   = (const float*)d_in[8];
    const float* bc2   = (const float*)d_in[9];
    const float* emb   = (const float*)d_in[10];
    const float* Wih0f = (const float*)d_in[11];
    const float* Whh0f = (const float*)d_in[12];
    const float* b0f   = (const float*)d_in[13];
    const float* Wih0b = (const float*)d_in[14];
    const float* Whh0b = (const float*)d_in[15];
    const float* b0b   = (const float*)d_in[16];
    const float* Wih1f = (const float*)d_in[17];
    const float* Whh1f = (const float*)d_in[18];
    const float* b1f   = (const float*)d_in[19];
    const float* Wih1b = (const float*)d_in[20];
    const float* Whh1b = (const float*)d_in[21];
    const float* b1b   = (const float*)d_in[22];
    const float* Wfc   = (const float*)d_in[23];
    const float* bfc   = (const float*)d_in[24];
    float* outp = (float*)d_out;

    float *p_tmp, *p_h0, *p_c0, *p_x0, *p_xg0, *p_out1, *p_W0T, *p_W1T;
    cudaGetSymbolAddress((void**)&p_tmp,  g_tmp);
    cudaGetSymbolAddress((void**)&p_h0,   g_h0);
    cudaGetSymbolAddress((void**)&p_c0,   g_c0);
    cudaGetSymbolAddress((void**)&p_x0,   g_x0);
    cudaGetSymbolAddress((void**)&p_xg0,  g_xg0);
    cudaGetSymbolAddress((void**)&p_out1, g_out1);
    cudaGetSymbolAddress((void**)&p_W0T,  g_W0T);
    cudaGetSymbolAddress((void**)&p_W1T,  g_W1T);

    const size_t W1ROW = (size_t)H4 * (Hc + H2);

    dim3 tb(32, 8);
    // Wfc -> transposed bf16 hi/lo (off the recurrent critical path)
    convB_k<<<dim3((Vc + 31) / 32, H2 / 32), tb>>>(Wfc);

    transpose_s<<<dim3(H4/32, Hc/32), tb>>>(Whh0f, p_W0T,                 Hc, H4, Hc);
    transpose_s<<<dim3(H4/32, Hc/32), tb>>>(Whh0b, p_W0T + (size_t)H4*Hc, Hc, H4, Hc);
    transpose_s<<<dim3(H4/32, Hc/32), tb>>>(Whh1f, p_W1T,                 Hc, H4, Hc + H2);
    transpose_s<<<dim3(H4/32, H2/32), tb>>>(Wih1f, p_W1T + Hc,            H2, H4, Hc + H2);
    transpose_s<<<dim3(H4/32, Hc/32), tb>>>(Whh1b, p_W1T + W1ROW,         Hc, H4, Hc + H2);
    transpose_s<<<dim3(H4/32, H2/32), tb>>>(Wih1b, p_W1T + W1ROW + Hc,    H2, H4, Hc + H2);

    // image MLPs
    sgemm_kernel<<<dim3(H2/64, 1), 256>>>(img,   Wh1, bh1, p_tmp, Bc, H2, Fc, 1);
    sgemm_kernel<<<dim3(Hc/64, 1), 256>>>(p_tmp, Wh2, bh2, p_h0,  Bc, Hc, H2, 1);
    sgemm_kernel<<<dim3(H2/64, 1), 256>>>(img,   Wc1, bc1, p_tmp, Bc, H2, Fc, 1);
    sgemm_kernel<<<dim3(Hc/64, 1), 256>>>(p_tmp, Wc2, bc2, p_c0,  Bc, Hc, H2, 1);
    bcast_state_k<<<(Hc*Bc + 255)/256, 256>>>();

    // embeddings + layer0 input gates
    gather_k<<<NTB, 256>>>(caps, emb);
    gemm128<<<dim3((H4+127)/128, (NTB+127)/128), 256>>>(p_x0, Wih0f, b0f, p_xg0,                    NTB, H4, Ec);
    gemm128<<<dim3((H4+127)/128, (NTB+127)/128), 256>>>(p_x0, Wih0b, b0b, p_xg0 + (size_t)NTB * H4, NTB, H4, Ec);

    // persistent recurrent chain
    const int SMEM_BYTES = (1536 * HSTRIDE + 32 * 8 * 16) * 4;
    cudaFuncSetAttribute(lstm_persist, cudaFuncAttributeMaxDynamicSharedMemorySize, SMEM_BYTES);
    lstm_persist<<<NBLK, 256, SMEM_BYTES>>>(b1f, b1b);

    // out1 -> bf16 hi/lo, then tensor-core FC (mma.sync HMMA)
    convA_k<<<(NTB*H2 + 255)/256, 256>>>(p_out1);
    cudaFuncSetAttribute(fc_wmma, cudaFuncAttributeMaxDynamicSharedMemorySize, FC_SMEM);
    fc_wmma<<<dim3((Vc + FCBN - 1)/FCBN, (NTB + FCBM - 1)/FCBM), 256, FC_SMEM>>>(bfc, outp);
}

// round 8
// speedup vs baseline: 2.6815x; 1.4802x over previous
#include <cuda_runtime.h>
#include <cuda_bf16.h>
#include <math.h>
#include <stdint.h>

// Problem constants
#define Bc 16
#define Nc 5
#define Tc 10
#define Hc 512
#define Ec 250
#define Vc 30000
#define Fc 2048
#define H4 2048
#define H2 1024
#define NTB (Nc*Tc*Bc)   // 800
#define NBLK 128

// packed fp32x2 FMA (SASS FFMA2)
#define FMA2(d, a, b) asm("fma.rn.f32x2 %0, %1, %2, %0;" : "+l"(d) : "l"(a), "l"(b))

__device__ __forceinline__ float f2lo(unsigned long long v) { return __uint_as_float((unsigned)v); }
__device__ __forceinline__ float f2hi(unsigned long long v) { return __uint_as_float((unsigned)(v >> 32)); }
__device__ __forceinline__ unsigned long long splat2(float w) {
    unsigned long long d;
    asm("mov.b64 %0, {%1, %1};" : "=l"(d) : "r"(__float_as_uint(w)));
    return d;
}

// hs bank-swizzled slot address: (k, q) -> byte offset; q = b-group (4 floats)
__device__ __forceinline__ int hs_off(int k, int q) {
    return (((k) << 6) | ((q) << 4)) ^ ((k & 0x1C) << 2);
}

// ---------------- device scratch ----------------
__device__ __align__(16) float g_tmp[Bc*H2];
__device__ __align__(16) float g_tmp2[Bc*H2];
__device__ __align__(16) float g_h0[Bc*Hc];
__device__ __align__(16) float g_c0[Bc*Hc];
__device__ __align__(16) float g_hst[4][2][Hc*Bc];
__device__ __align__(16) float g_cst[4][Hc*Bc];
__device__ __align__(16) float g_x0[NTB*Ec];
__device__ __align__(16) float g_xg0[2*NTB*H4];
__device__ __align__(16) float g_x1[Tc*H2*Bc];
__device__ __align__(16) float g_out1[NTB*H2];
__device__ __align__(16) float g_W0T[2*H4*Hc];
__device__ __align__(16) float g_W1T[2*H4*(Hc+H2)];
__device__ __align__(16) __nv_bfloat16 g_Ahi[NTB*H2];
__device__ __align__(16) __nv_bfloat16 g_Alo[NTB*H2];
__device__ __align__(16) __nv_bfloat16 g_Bhi[(size_t)Vc*H2];
__device__ __align__(16) __nv_bfloat16 g_Blo[(size_t)Vc*H2];

__device__ unsigned g_barcnt = 0;
__device__ unsigned g_barsense = 0;

// ================= small fp32 GEMM, dual problem select by blockIdx.z =================
__global__ __launch_bounds__(256) void sgemm_dual(
    const float* __restrict__ A0, const float* __restrict__ W0,
    const float* __restrict__ bias0, float* __restrict__ C0,
    const float* __restrict__ A1, const float* __restrict__ W1,
    const float* __restrict__ bias1, float* __restrict__ C1,
    int M, int N, int K, int relu)
{
    const float* A = blockIdx.z ? A1 : A0;
    const float* W = blockIdx.z ? W1 : W0;
    const float* bias = blockIdx.z ? bias1 : bias0;
    float* C = blockIdx.z ? C1 : C0;

    __shared__ float As[16][64];
    __shared__ float Bs[16][64];
    int bm = blockIdx.y * 64, bn = blockIdx.x * 64;
    int tid = threadIdx.x;
    int tm = (tid >> 4) << 2;
    int tn = (tid & 15) << 2;
    float acc[4][4] = {};
    for (int k0 = 0; k0 < K; k0 += 16) {
        #pragma unroll
        for (int e = 0; e < 4; e++) {
            int idx = tid + e * 256;
            int r = idx >> 4, c = idx & 15;
            int gr = bm + r, gc = k0 + c;
            float v = 0.f;
            if (gr < M && gc < K) v = A[(size_t)gr * K + gc];
            As[c][r] = v;
        }
        #pragma unroll
        for (int e = 0; e < 4; e++) {
            int idx = tid + e * 256;
            int r = idx >> 6, c = idx & 63;
            int gr = k0 + r, gc = bn + c;
            float v = 0.f;
            if (gr < K && gc < N) v = W[(size_t)gr * N + gc];
            Bs[r][c] = v;
        }
        __syncthreads();
        #pragma unroll
        for (int kk = 0; kk < 16; kk++) {
            float4 a4 = *(const float4*)&As[kk][tm];
            float4 b4 = *(const float4*)&Bs[kk][tn];
            float a[4] = {a4.x, a4.y, a4.z, a4.w};
            float b[4] = {b4.x, b4.y, b4.z, b4.w};
            #pragma unroll
            for (int i = 0; i < 4; i++)
                #pragma unroll
                for (int j = 0; j < 4; j++)
                    acc[i][j] = fmaf(a[i], b[j], acc[i][j]);
        }
        __syncthreads();
    }
    #pragma unroll
    for (int i = 0; i < 4; i++) {
        int gm = bm + tm + i;
        if (gm >= M) continue;
        #pragma unroll
        for (int j = 0; j < 4; j++) {
            int gn = bn + tn + j;
            if (gn >= N) continue;
            float v = acc[i][j] + bias[gn];
            if (relu) v = fmaxf(v, 0.f);
            C[(size_t)gm * N + gn] = v;
        }
    }
}

// ================= fp32 GEMM 128x128 dual (xg0, both dirs) =================
__global__ __launch_bounds__(256, 2) void gemm128_dual(
    const float* __restrict__ A,
    const float* __restrict__ B0, const float* __restrict__ bias0, float* __restrict__ C0,
    const float* __restrict__ B1, const float* __restrict__ bias1, float* __restrict__ C1,
    int M, int N, int K)
{
    const float* B = blockIdx.z ? B1 : B0;
    const float* bias = blockIdx.z ? bias1 : bias0;
    float* C = blockIdx.z ? C1 : C0;

    __shared__ __align__(16) float As[2][16][128];
    __shared__ __align__(16) float Bs[2][16][256];

    int tid = threadIdx.x;
    int bm = blockIdx.y * 128, bn = blockIdx.x * 128;
    int tx = tid & 15, ty = tid >> 4;
    int ar = tid >> 2, ac = (tid & 3) * 4;
    int br = tid >> 5, bc = (tid & 31) * 4;

    bool fullM = (bm + 128 <= M);
    bool fullN = (bn + 128 <= N);
    bool alnA  = ((K & 3) == 0);

    unsigned long long acc[4][8];
    #pragma unroll
    for (int i = 0; i < 4; i++)
        #pragma unroll
        for (int j = 0; j < 8; j++) acc[i][j] = 0ull;

    float a0[4], a1[4], b0[4], b1[4];
    int KT = (K + 15) / 16;

#define LOADTILE(KT_) do {                                                        \
    int k0 = (KT_) * 16;                                                          \
    bool fk = (k0 + 16 <= K);                                                     \
    if (fk && fullM && alnA) {                                                    \
        float4 r0 = *(const float4*)&A[(size_t)(bm + ar) * K + k0 + ac];          \
        float4 r1 = *(const float4*)&A[(size_t)(bm + ar + 64) * K + k0 + ac];     \
        a0[0]=r0.x; a0[1]=r0.y; a0[2]=r0.z; a0[3]=r0.w;                           \
        a1[0]=r1.x; a1[1]=r1.y; a1[2]=r1.z; a1[3]=r1.w;                           \
    } else {                                                                      \
        int gr0 = bm + ar, gr1 = bm + ar + 64;                                    \
        _Pragma("unroll") for (int j = 0; j < 4; j++) {                           \
            int gk = k0 + ac + j;                                                 \
            bool ok = (gk < K);                                                   \
            a0[j] = (ok && gr0 < M) ? A[(size_t)gr0 * K + gk] : 0.f;              \
            a1[j] = (ok && gr1 < M) ? A[(size_t)gr1 * K + gk] : 0.f;              \
        }                                                                         \
    }                                                                             \
    if (fk && fullN) {                                                            \
        float4 r0 = *(const float4*)&B[(size_t)(k0 + br) * N + bn + bc];          \
        float4 r1 = *(const float4*)&B[(size_t)(k0 + br + 8) * N + bn + bc];      \
        b0[0]=r0.x; b0[1]=r0.y; b0[2]=r0.z; b0[3]=r0.w;                           \
        b1[0]=r1.x; b1[1]=r1.y; b1[2]=r1.z; b1[3]=r1.w;                           \
    } else {                                                                      \
        int gk0 = k0 + br, gk1 = k0 + br + 8;                                     \
        _Pragma("unroll") for (int j = 0; j < 4; j++) {                           \
            int gc = bn + bc + j;                                                 \
            bool ok = (gc < N);                                                   \
            b0[j] = (ok && gk0 < K) ? B[(size_t)gk0 * N + gc] : 0.f;              \
            b1[j] = (ok && gk1 < K) ? B[(size_t)gk1 * N + gc] : 0.f;              \
        }                                                                         \
    }                                                                             \
} while (0)

#define STORETILE(BUF_) do {                                                      \
    _Pragma("unroll") for (int j = 0; j < 4; j++) {                               \
        As[BUF_][ac + j][ar]      = a0[j];                                        \
        As[BUF_][ac + j][ar + 64] = a1[j];                                        \
        Bs[BUF_][br][(bc + j) * 2]         = b0[j];                               \
        Bs[BUF_][br][(bc + j) * 2 + 1]     = b0[j];                               \
        Bs[BUF_][br + 8][(bc + j) * 2]     = b1[j];                               \
        Bs[BUF_][br + 8][(bc + j) * 2 + 1] = b1[j];                               \
    }                                                                             \
} while (0)

    LOADTILE(0);
    STORETILE(0);
    __syncthreads();

    for (int kt = 0; kt < KT; kt++) {
        int cur = kt & 1;
        if (kt + 1 < KT) LOADTILE(kt + 1);
        #pragma unroll
        for (int k = 0; k < 16; k++) {
            unsigned long long a2[4], b2[8];
            #pragma unroll
            for (int i = 0; i < 4; i++)
                a2[i] = *(const unsigned long long*)&As[cur][k][ty * 8 + 2 * i];
            #pragma unroll
            for (int j = 0; j < 8; j++)
                b2[j] = *(const unsigned long long*)&Bs[cur][k][(tx + 16 * j) * 2];
            #pragma unroll
            for (int i = 0; i < 4; i++)
                #pragma unroll
                for (int j = 0; j < 8; j++)
                    FMA2(acc[i][j], a2[i], b2[j]);
        }
        if (kt + 1 < KT) STORETILE(cur ^ 1);
        __syncthreads();
    }

    #pragma unroll
    for (int j = 0; j < 8; j++) {
        int col = bn + tx + 16 * j;
        if (col >= N) continue;
        float bb = bias[col];
        #pragma unroll
        for (int i = 0; i < 4; i++) {
            int r0 = bm + ty * 8 + 2 * i;
            float lo = f2lo(acc[i][j]) + bb;
            float hi = f2hi(acc[i][j]) + bb;
            if (r0 < M)     C[(size_t)r0 * N + col] = lo;
            if (r0 + 1 < M) C[(size_t)(r0 + 1) * N + col] = hi;
        }
    }
#undef LOADTILE
#undef STORETILE
}

// ================= bf16-split mma.sync FC =================
#define FCBM 128
#define FCBN 128
#define FCBK 64
#define PADK 72
#define FC_SMEM (4 * FCBM * PADK * 2)

__device__ __forceinline__ void mma16816(
    float& c0, float& c1, float& c2, float& c3,
    uint32_t a0, uint32_t a1, uint32_t a2, uint32_t a3,
    uint32_t b0, uint32_t b1)
{
    asm volatile(
        "mma.sync.aligned.m16n8k16.row.col.f32.bf16.bf16.f32 "
        "{%0,%1,%2,%3}, {%4,%5,%6,%7}, {%8,%9}, {%0,%1,%2,%3};"
        : "+f"(c0), "+f"(c1), "+f"(c2), "+f"(c3)
        : "r"(a0), "r"(a1), "r"(a2), "r"(a3), "r"(b0), "r"(b1));
}

__global__ __launch_bounds__(256) void fc_wmma(
    const float* __restrict__ bias, float* __restrict__ out)
{
    extern __shared__ __align__(16) __nv_bfloat16 sm[];
    __nv_bfloat16* sAh = sm;
    __nv_bfloat16* sAl = sm + FCBM * PADK;
    __nv_bfloat16* sBh = sm + 2 * FCBM * PADK;
    __nv_bfloat16* sBl = sm + 3 * FCBM * PADK;

    int tid = threadIdx.x;
    int wid = tid >> 5, lane = tid & 31;
    int g = lane >> 2, q = lane & 3;
    int wm = wid & 3, wn = wid >> 2;
    int bm = blockIdx.y * FCBM, bn = blockIdx.x * FCBN;

    const uint4* A4h = (const uint4*)g_Ahi;
    const uint4* A4l = (const uint4*)g_Alo;
    const uint4* B4h = (const uint4*)g_Bhi;
    const uint4* B4l = (const uint4*)g_Blo;
    const uint4 z4 = make_uint4(0, 0, 0, 0);

    float acc[2][8][4];
    #pragma unroll
    for (int i = 0; i < 2; i++)
        #pragma unroll
        for (int j = 0; j < 8; j++)
            #pragma unroll
            for (int e = 0; e < 4; e++) acc[i][j][e] = 0.f;

    const uint32_t* sA32h = (const uint32_t*)sAh;
    const uint32_t* sA32l = (const uint32_t*)sAl;
    const uint32_t* sB32h = (const uint32_t*)sBh;
    const uint32_t* sB32l = (const uint32_t*)sBl;

    for (int kc = 0; kc < H2 / FCBK; kc++) {
        __syncthreads();
        #pragma unroll
        for (int it = 0; it < 4; it++) {
            int idx = tid + it * 256;
            int m = idx >> 3, kg = idx & 7;
            int gm = bm + m;
            size_t gi = (size_t)gm * (H2 / 8) + kc * 8 + kg;
            uint4 vh = z4, vl = z4;
            if (gm < NTB) { vh = A4h[gi]; vl = A4l[gi]; }
            *(uint4*)&sAh[m * PADK + kg * 8] = vh;
            *(uint4*)&sAl[m * PADK + kg * 8] = vl;
        }
        #pragma unroll
        for (int it = 0; it < 4; it++) {
            int idx = tid + it * 256;
            int n = idx >> 3, kg = idx & 7;
            int gn = bn + n;
            uint4 vh = z4, vl = z4;
            if (gn < Vc) {
                size_t gi = (size_t)gn * (H2 / 8) + kc * 8 + kg;
                vh = B4h[gi]; vl = B4l[gi];
            }
            *(uint4*)&sBh[n * PADK + kg * 8] = vh;
            *(uint4*)&sBl[n * PADK + kg * 8] = vl;
        }
        __syncthreads();

        #pragma unroll
        for (int ks = 0; ks < 4; ks++) {
            uint32_t ah[2][4], al[2][4];
            #pragma unroll
            for (int mi = 0; mi < 2; mi++) {
                int r0 = (wm * 32 + mi * 16 + g) * (PADK / 2);
                int r8 = r0 + 8 * (PADK / 2);
                int w0 = ks * 8 + q, w4 = w0 + 4;
                ah[mi][0] = sA32h[r0 + w0]; ah[mi][1] = sA32h[r8 + w0];
                ah[mi][2] = sA32h[r0 + w4]; ah[mi][3] = sA32h[r8 + w4];
                al[mi][0] = sA32l[r0 + w0]; al[mi][1] = sA32l[r8 + w0];
                al[mi][2] = sA32l[r0 + w4]; al[mi][3] = sA32l[r8 + w4];
            }
            #pragma unroll
            for (int ni = 0; ni < 8; ni++) {
                int nr = (wn * 64 + ni * 8 + g) * (PADK / 2);
                int w0 = ks * 8 + q, w4 = w0 + 4;
                uint32_t bh0 = sB32h[nr + w0], bh1 = sB32h[nr + w4];
                uint32_t bl0 = sB32l[nr + w0], bl1 = sB32l[nr + w4];
                #pragma unroll
                for (int mi = 0; mi < 2; mi++) {
                    float* c = acc[mi][ni];
                    mma16816(c[0], c[1], c[2], c[3],
                             ah[mi][0], ah[mi][1], ah[mi][2], ah[mi][3], bh0, bh1);
                    mma16816(c[0], c[1], c[2], c[3],
                             al[mi][0], al[mi][1], al[mi][2], al[mi][3], bh0, bh1);
                    mma16816(c[0], c[1], c[2], c[3],
                             ah[mi][0], ah[mi][1], ah[mi][2], ah[mi][3], bl0, bl1);
                }
            }
        }
    }

    #pragma unroll
    for (int mi = 0; mi < 2; mi++) {
        int row0 = bm + wm * 32 + mi * 16 + g;
        int row1 = row0 + 8;
        #pragma unroll
        for (int ni = 0; ni < 8; ni++) {
            int col = bn + wn * 64 + ni * 8 + q * 2;
            if (col >= Vc) continue;
            float b0 = bias[col], b1 = bias[col + 1];
            const float* c = acc[mi][ni];
            if (row0 < NTB) {
                float2 v = make_float2(c[0] + b0, c[1] + b1);
                *(float2*)&out[(size_t)row0 * Vc + col] = v;
            }
            if (row1 < NTB) {
                float2 v = make_float2(c[2] + b0, c[3] + b1);
                *(float2*)&out[(size_t)row1 * Vc + col] = v;
            }
        }
    }
}

// ---------------- bf16 split conversions ----------------
__global__ void convA_k(const float* __restrict__ in)
{
    int i = blockIdx.x * 256 + threadIdx.x;
    if (i < NTB * H2) {
        float v = in[i];
        __nv_bfloat16 h = __float2bfloat16(v);
        g_Ahi[i] = h;
        g_Alo[i] = __float2bfloat16(v - __bfloat162float(h));
    }
}

__global__ void convB_k(const float* __restrict__ W)
{
    __shared__ float t[32][33];
    int n0 = blockIdx.x * 32, k0 = blockIdx.y * 32;
    for (int j = threadIdx.y; j < 32; j += 8) {
        int k = k0 + j, n = n0 + threadIdx.x;
        t[j][threadIdx.x] = (n < Vc) ? W[(size_t)k * Vc + n] : 0.f;
    }
    __syncthreads();
    for (int j = threadIdx.y; j < 32; j += 8) {
        int n = n0 + j, k = k0 + threadIdx.x;
        if (n < Vc) {
            float v = t[threadIdx.x][j];
            __nv_bfloat16 h = __float2bfloat16(v);
            g_Bhi[(size_t)n * H2 + k] = h;
            g_Blo[(size_t)n * H2 + k] = __float2bfloat16(v - __bfloat162float(h));
        }
    }
}

// ---------------- fused 6-way transpose ----------------
struct TParam { const float* in; float* out; int R; int ostride; };
struct TParams6 { TParam p[6]; };

__global__ void transpose_all(TParams6 ps)
{
    const TParam tp = ps.p[blockIdx.z];
    const int C = H4;
    __shared__ float tile[32][33];
    int c0 = blockIdx.x * 32, r0 = blockIdx.y * 32;
    if (r0 >= tp.R) return;
    for (int j = threadIdx.y; j < 32; j += 8) {
        int r = r0 + j, c = c0 + threadIdx.x;
        tile[j][threadIdx.x] = (r < tp.R) ? tp.in[(size_t)r * C + c] : 0.f;
    }
    __syncthreads();
    for (int j = threadIdx.y; j < 32; j += 8) {
        int c = c0 + j, r = r0 + threadIdx.x;
        if (r < tp.R) tp.out[(size_t)c * tp.ostride + r] = tile[threadIdx.x][j];
    }
}

// ---------------- fused broadcast + gather ----------------
__global__ void bcast_gather_k(const int* __restrict__ caps, const float* __restrict__ emb)
{
    if (blockIdx.x < 32) {
        int i = blockIdx.x * 256 + threadIdx.x;
        if (i < Hc * Bc) {
            int k = i >> 4, b = i & 15;
            float h = g_h0[b * Hc + k];
            float c = g_c0[b * Hc + k];
            #pragma unroll
            for (int s = 0; s < 4; s++) {
                g_hst[s][0][i] = h;
                g_cst[s][i]    = c;
            }
        }
    } else {
        int rid = blockIdx.x - 32;            // 0..799
        int b = rid & 15;
        int nt = rid >> 4;
        int n = nt / Tc, t = nt % Tc;
        int tok = caps[b * (Nc * Tc) + n * Tc + t];
        const float* e = emb + (size_t)tok * Ec;
        float* o = g_x0 + (size_t)rid * Ec;
        for (int i = threadIdx.x; i < Ec; i += blockDim.x) o[i] = e[i];
    }
}

// ================= persistent recurrent kernel =================
__device__ __forceinline__ void grid_bar(unsigned& sense)
{
    __syncthreads();
    sense ^= 1;
    if (threadIdx.x == 0) {
        __threadfence();
        unsigned old = atomicAdd(&g_barcnt, 1);
        if (old == NBLK - 1) {
            g_barcnt = 0;
            __threadfence();
            atomicExch(&g_barsense, sense);
        } else {
            while (*(volatile unsigned*)&g_barsense != sense) __nanosleep(32);
        }
        __threadfence();
    }
    __syncthreads();
}

template<int LAYER>
__device__ __forceinline__ void lstm_do_step(
    int tid, int dir, int bkid, int ksub, int bs, int rg,
    char* hsb, float* red,
    int n, int tok, int par,
    const float* bias1, const float* xg0d, unsigned& sense)
{
    const int K = LAYER ? (Hc + H2) : Hc;
    int slot = LAYER ? (2 + dir) : dir;
    const float* hglob = &g_hst[slot][par][0];
    float* hout = &g_hst[slot][par ^ 1][0];
    float* cst  = &g_cst[slot][0];
    const float* WT = LAYER ? (g_W1T + (size_t)dir * H4 * (Hc + H2))
                            : (g_W0T + (size_t)dir * H4 * Hc);

    // stage A: stage h (and x1 for layer1) into bank-swizzled smem
    {
        const float* x1g = g_x1 + (size_t)tok * H2 * Bc;
        int nf4 = K * 4;
        for (int idx = tid; idx < nf4; idx += 256) {
            int k = idx >> 2, q = idx & 3;
            float4 v;
            if (!LAYER || k < Hc) v = *(const float4*)&hglob[k * Bc + q * 4];
            else                  v = *(const float4*)&x1g[(size_t)(k - Hc) * Bc + q * 4];
            *(float4*)(hsb + hs_off(k, q)) = v;
        }
    }
    __syncthreads();

    // stage B: partial dots with register-double-buffered weight loads
    int r0 = rg * 4;
    const float4* p0;
    const float4* p1;
    const float4* p2;
    const float4* p3;
    {
        int m0 = ((r0 + 0) >> 3) * Hc + bkid * 8 + ((r0 + 0) & 7);
        int m1 = ((r0 + 1) >> 3) * Hc + bkid * 8 + ((r0 + 1) & 7);
        int m2 = ((r0 + 2) >> 3) * Hc + bkid * 8 + ((r0 + 2) & 7);
        int m3 = ((r0 + 3) >> 3) * Hc + bkid * 8 + ((r0 + 3) & 7);
        p0 = (const float4*)(WT + (size_t)m0 * K);
        p1 = (const float4*)(WT + (size_t)m1 * K);
        p2 = (const float4*)(WT + (size_t)m2 * K);
        p3 = (const float4*)(WT + (size_t)m3 * K);
    }
    unsigned long long a00 = 0, a01 = 0, a10 = 0, a11 = 0,
                       a20 = 0, a21 = 0, a30 = 0, a31 = 0;
    const int K32 = K / 32;
    float4 c0 = p0[ksub], c1 = p1[ksub], c2 = p2[ksub], c3 = p3[ksub];
    #pragma unroll 2
    for (int i = 0; i < K32; i++) {
        int nf = ((i + 1 < K32) ? (i + 1) : i) * 8 + ksub;
        float4 n0 = p0[nf], n1 = p1[nf], n2 = p2[nf], n3 = p3[nf];
        int kb = i * 32 + ksub * 4;
        const float* wp0 = (const float*)&c0;
        const float* wp1 = (const float*)&c1;
        const float* wp2 = (const float*)&c2;
        const float* wp3 = (const float*)&c3;
        #pragma unroll
        for (int kk = 0; kk < 4; kk++) {
            ulonglong2 hv = *(const ulonglong2*)(hsb + hs_off(kb + kk, bs));
            unsigned long long s0 = splat2(wp0[kk]);
            unsigned long long s1 = splat2(wp1[kk]);
            unsigned long long s2 = splat2(wp2[kk]);
            unsigned long long s3 = splat2(wp3[kk]);
            FMA2(a00, s0, hv.x); FMA2(a01, s0, hv.y);
            FMA2(a10, s1, hv.x); FMA2(a11, s1, hv.y);
            FMA2(a20, s2, hv.x); FMA2(a21, s2, hv.y);
            FMA2(a30, s3, hv.x); FMA2(a31, s3, hv.y);
        }
        c0 = n0; c1 = n1; c2 = n2; c3 = n3;
    }

    // stage C: dump partials
    {
        float4 v;
        v = make_float4(f2lo(a00), f2hi(a00), f2lo(a01), f2hi(a01));
        *(float4*)&red[((r0 + 0) * 8 + ksub) * 16 + bs * 4] = v;
        v = make_float4(f2lo(a10), f2hi(a10), f2lo(a11), f2hi(a11));
        *(float4*)&red[((r0 + 1) * 8 + ksub) * 16 + bs * 4] = v;
        v = make_float4(f2lo(a20), f2hi(a20), f2lo(a21), f2hi(a21));
        *(float4*)&red[((r0 + 2) * 8 + ksub) * 16 + bs * 4] = v;
        v = make_float4(f2lo(a30), f2hi(a30), f2lo(a31), f2hi(a31));
        *(float4*)&red[((r0 + 3) * 8 + ksub) * 16 + bs * 4] = v;
    }
    __syncthreads();

    // stage D: reduce + nonlinearity + state update
    if (tid < 128) {
        int ko_l = tid & 7, b = tid >> 3;
        int ko = bkid * 8 + ko_l;
        float gsum[4];
        #pragma unroll
        for (int g = 0; g < 4; g++) {
            int r = g * 8 + ko_l;
            float ss = 0.f;
            #pragma unroll
            for (int ks = 0; ks < 8; ks++) ss += red[(r * 8 + ks) * 16 + b];
            gsum[g] = ss;
        }
        float pi, pf, pg, po;
        if (LAYER) {
            pi = bias1[ko]; pf = bias1[512 + ko];
            pg = bias1[1024 + ko]; po = bias1[1536 + ko];
        } else {
            const float* xg = xg0d + ((size_t)(n * Tc + tok) * Bc + b) * H4 + ko;
            pi = xg[0]; pf = xg[512]; pg = xg[1024]; po = xg[1536];
        }
        float gi = gsum[0] + pi, gf = gsum[1] + pf, gg = gsum[2] + pg, go = gsum[3] + po;
        float si = 1.f / (1.f + expf(-gi));
        float sf = 1.f / (1.f + expf(-gf));
        float so = 1.f / (1.f + expf(-go));
        int idx = ko * Bc + b;
        float cn = sf * cst[idx] + si * tanhf(gg);
        float hn = so * tanhf(cn);
        cst[idx]  = cn;
        hout[idx] = hn;
        if (LAYER) {
            g_out1[((size_t)(n * Tc + tok) * Bc + b) * H2 + dir * Hc + ko] = hn;
        } else {
            g_x1[((size_t)tok * H2 + dir * Hc + ko) * Bc + b] = hn;
        }
    }
    grid_bar(sense);
}

#define HS_BYTES ((Hc + H2) * 64)          // 98304
#define RED_FLOATS (32 * 8 * 16)           // 4096
#define LSTM_SMEM (HS_BYTES + RED_FLOATS * 4)

__global__ __launch_bounds__(256, 1) void lstm_persist(
    const float* __restrict__ b1f_, const float* __restrict__ b1b_)
{
    extern __shared__ __align__(16) char smemc[];
    char* hsb  = smemc;
    float* red = (float*)(smemc + HS_BYTES);

    int tid = threadIdx.x, bid = blockIdx.x;
    int dir = bid >> 6, bkid = bid & 63;
    int ksub = tid & 7, bs = (tid >> 3) & 3, rg = tid >> 5;

    const float* bias1 = dir ? b1b_ : b1f_;
    const float* xg0d  = g_xg0 + (size_t)dir * NTB * H4;

    unsigned sense = 0;
    int p0 = 0, p1 = 0;

    for (int t = 0; t < Tc; t++) {
        for (int n = 0; n < Nc; n++) {
            int L = t + 1;
            for (int s = 0; s < L; s++) {
                int tok = dir ? (L - 1 - s) : s;
                lstm_do_step<0>(tid, dir, bkid, ksub, bs, rg, hsb, red,
                                n, tok, p0, bias1, xg0d, sense);
                p0 ^= 1;
            }
            for (int s = 0; s < L; s++) {
                int tok = dir ? (L - 1 - s) : s;
                lstm_do_step<1>(tid, dir, bkid, ksub, bs, rg, hsb, red,
                                n, tok, p1, bias1, xg0d, sense);
                p1 ^= 1;
            }
        }
    }
}

// ---------------- host ----------------
extern "C" void kernel_launch(void* const* d_in, const int* in_sizes, int n_in,
                              void* d_out, int out_size)
{
    const float* img   = (const float*)d_in[0];
    const int*   caps  = (const int*)  d_in[1];
    const float* Wh1   = (const float*)d_in[2];
    const float* bh1   = (const float*)d_in[3];
    const float* Wh2   = (const float*)d_in[4];
    const float* bh2   = (const float*)d_in[5];
    const float* Wc1   = (const float*)d_in[6];
    const float* bc1   = (const float*)d_in[7];
    const float* Wc2   = (const float*)d_in[8];
    const float* bc2   = (const float*)d_in[9];
    const float* emb   = (const float*)d_in[10];
    const float* Wih0f = (const float*)d_in[11];
    const float* Whh0f = (const float*)d_in[12];
    const float* b0f   = (const float*)d_in[13];
    const float* Wih0b = (const float*)d_in[14];
    const float* Whh0b = (const float*)d_in[15];
    const float* b0b   = (const float*)d_in[16];
    const float* Wih1f = (const float*)d_in[17];
    const float* Whh1f = (const float*)d_in[18];
    const float* b1f   = (const float*)d_in[19];
    const float* Wih1b = (const float*)d_in[20];
    const float* Whh1b = (const float*)d_in[21];
    const float* b1b   = (const float*)d_in[22];
    const float* Wfc   = (const float*)d_in[23];
    const float* bfc   = (const float*)d_in[24];
    float* outp = (float*)d_out;

    float *p_tmp, *p_tmp2, *p_h0, *p_c0, *p_x0, *p_xg0, *p_out1, *p_W0T, *p_W1T;
    cudaGetSymbolAddress((void**)&p_tmp,  g_tmp);
    cudaGetSymbolAddress((void**)&p_tmp2, g_tmp2);
    cudaGetSymbolAddress((void**)&p_h0,   g_h0);
    cudaGetSymbolAddress((void**)&p_c0,   g_c0);
    cudaGetSymbolAddress((void**)&p_x0,   g_x0);
    cudaGetSymbolAddress((void**)&p_xg0,  g_xg0);
    cudaGetSymbolAddress((void**)&p_out1, g_out1);
    cudaGetSymbolAddress((void**)&p_W0T,  g_W0T);
    cudaGetSymbolAddress((void**)&p_W1T,  g_W1T);

    const size_t W1ROW = (size_t)H4 * (Hc + H2);

    // Launch 1: all six weight transposes
    TParams6 tp;
    tp.p[0] = { Whh0f, p_W0T,                 Hc, Hc };
    tp.p[1] = { Whh0b, p_W0T + (size_t)H4*Hc, Hc, Hc };
    tp.p[2] = { Whh1f, p_W1T,                 Hc, Hc + H2 };
    tp.p[3] = { Wih1f, p_W1T + Hc,            H2, Hc + H2 };
    tp.p[4] = { Whh1b, p_W1T + W1ROW,         Hc, Hc + H2 };
    tp.p[5] = { Wih1b, p_W1T + W1ROW + Hc,    H2, Hc + H2 };
    transpose_all<<<dim3(H4/32, 32, 6), dim3(32, 8)>>>(tp);

    // Launch 2-3: image MLPs (h and c chains in parallel via z)
    sgemm_dual<<<dim3(H2/64, 1, 2), 256>>>(img, Wh1, bh1, p_tmp,
                                           img, Wc1, bc1, p_tmp2, Bc, H2, Fc, 1);
    sgemm_dual<<<dim3(Hc/64, 1, 2), 256>>>(p_tmp,  Wh2, bh2, p_h0,
                                           p_tmp2, Wc2, bc2, p_c0, Bc, Hc, H2, 1);

    // Launch 4: state broadcast + embedding gather
    bcast_gather_k<<<32 + NTB, 256>>>(caps, emb);

    // Launch 5: layer0 input gates, both dirs
    gemm128_dual<<<dim3(H4/128, (NTB+127)/128, 2), 256>>>(
        p_x0, Wih0f, b0f, p_xg0, Wih0b, b0b, p_xg0 + (size_t)NTB * H4, NTB, H4, Ec);

    // Launch 6: persistent recurrent chain (profiled by ncu -s 5 -c 1)
    cudaFuncSetAttribute(lstm_persist, cudaFuncAttributeMaxDynamicSharedMemorySize, LSTM_SMEM);
    lstm_persist<<<NBLK, 256, LSTM_SMEM>>>(b1f, b1b);

    // Launch 7-9: FC path
    convB_k<<<dim3((Vc + 31) / 32, H2 / 32), dim3(32, 8)>>>(Wfc);
    convA_k<<<(NTB*H2 + 255)/256, 256>>>(p_out1);
    cudaFuncSetAttribute(fc_wmma, cudaFuncAttributeMaxDynamicSharedMemorySize, FC_SMEM);
    fc_wmma<<<dim3((Vc + FCBN - 1)/FCBN, (NTB + FCBM - 1)/FCBM), 256, FC_SMEM>>>(bfc, outp);
}